// round 4
// baseline (speedup 1.0000x reference)
#include <cuda_runtime.h>
#include <cuda_bf16.h>
#include <cstdint>
#include <cstddef>

// ---------------------------------------------------------------------------
// Problem constants
// ---------------------------------------------------------------------------
static constexpr int IN_DIM  = 3000;
static constexpr int IN_PAD  = 3008;    // K padded to multiple of 32
static constexpr int HID     = 512;
static constexpr int LAT     = 20;
static constexpr int M_REAL  = 100000;
static constexpr int M_PAD   = 100096;  // 782 * 128
static constexpr int MT      = 128;     // CTA M tile
static constexpr int BK      = 32;      // CTA K tile (bf16 elems)

// ---------------------------------------------------------------------------
// Static device scratch (allocation-free rule)
// Weights transposed to [N][K_pad] bf16 hi/lo, zero padded.
// Hidden activations as bf16 hi/lo pairs, rows padded to M_PAD.
// ---------------------------------------------------------------------------
__device__ __align__(16) __nv_bfloat16 g_W0h[HID * IN_PAD];
__device__ __align__(16) __nv_bfloat16 g_W0l[HID * IN_PAD];
__device__ __align__(16) __nv_bfloat16 g_W1h[HID * HID];
__device__ __align__(16) __nv_bfloat16 g_W1l[HID * HID];
__device__ __align__(16) __nv_bfloat16 g_W2h[HID * HID];
__device__ __align__(16) __nv_bfloat16 g_W2l[HID * HID];
__device__ __align__(16) __nv_bfloat16 g_W3h[32 * HID];
__device__ __align__(16) __nv_bfloat16 g_W3l[32 * HID];
__device__ __align__(16) __nv_bfloat16 g_Hah[(size_t)M_PAD * HID];
__device__ __align__(16) __nv_bfloat16 g_Hal[(size_t)M_PAD * HID];
__device__ __align__(16) __nv_bfloat16 g_Hbh[(size_t)M_PAD * HID];
__device__ __align__(16) __nv_bfloat16 g_Hbl[(size_t)M_PAD * HID];

// ---------------------------------------------------------------------------
// Helpers
// ---------------------------------------------------------------------------
__device__ __forceinline__ uint32_t smem_u32(const void* p) {
    uint32_t a;
    asm("{ .reg .u64 t; cvta.to.shared.u64 t, %1; cvt.u32.u64 %0, t; }"
        : "=r"(a) : "l"(p));
    return a;
}

__device__ __forceinline__ void cp16(uint32_t dst, const void* src) {
    asm volatile("cp.async.cg.shared.global [%0], [%1], 16;"
                 :: "r"(dst), "l"(src) : "memory");
}

__device__ __forceinline__ void ldsm4(uint32_t addr, uint32_t& r0, uint32_t& r1,
                                      uint32_t& r2, uint32_t& r3) {
    asm volatile("ldmatrix.sync.aligned.m8n8.x4.shared.b16 {%0,%1,%2,%3}, [%4];"
                 : "=r"(r0), "=r"(r1), "=r"(r2), "=r"(r3) : "r"(addr));
}

__device__ __forceinline__ void mma16816(float* c, const uint32_t* a, const uint32_t* b) {
    asm volatile(
        "mma.sync.aligned.m16n8k16.row.col.f32.bf16.bf16.f32 "
        "{%0,%1,%2,%3}, {%4,%5,%6,%7}, {%8,%9}, {%0,%1,%2,%3};"
        : "+f"(c[0]), "+f"(c[1]), "+f"(c[2]), "+f"(c[3])
        : "r"(a[0]), "r"(a[1]), "r"(a[2]), "r"(a[3]), "r"(b[0]), "r"(b[1]));
}

__device__ __forceinline__ void split1(float v, __nv_bfloat16& h, __nv_bfloat16& l) {
    h = __float2bfloat16(v);
    l = __float2bfloat16(v - __bfloat162float(h));
}

__device__ __forceinline__ uint32_t pack_bf2(__nv_bfloat16 a, __nv_bfloat16 b) {
    __nv_bfloat162 t(a, b);  // .x = a (low half)
    return *reinterpret_cast<uint32_t*>(&t);
}

// smem tile layout: rows of 64B (32 bf16), 4x16B chunks, XOR swizzle on (row>>1)&3
__device__ __forceinline__ uint32_t tile_off(int r, int c) {
    return (uint32_t)(r * 64 + ((c ^ ((r >> 1) & 3)) << 4));
}

// ---------------------------------------------------------------------------
// Weight prep: W[K][N] fp32 -> Wt[N_pad][K_pad] bf16 hi/lo, zero padded
// ---------------------------------------------------------------------------
__global__ void prep_w(const float* __restrict__ W,
                       __nv_bfloat16* __restrict__ dh,
                       __nv_bfloat16* __restrict__ dl,
                       int K, int N, int K_pad, int N_pad) {
    int idx = blockIdx.x * 256 + threadIdx.x;
    if (idx >= N_pad * K_pad) return;
    int n = idx / K_pad, k = idx - n * K_pad;
    float v = (n < N && k < K) ? W[(size_t)k * N + n] : 0.0f;
    __nv_bfloat16 h, l;
    split1(v, h, l);
    dh[idx] = h;
    dl[idx] = l;
}

// ---------------------------------------------------------------------------
// Split-bf16 (3-pass) GEMM + bias + ReLU via mma.sync m16n8k16
//   D[MT, BN] = Ah*Bh^T + Ah*Bl^T + Al*Bh^T   (fp32 accum in regs)
// 8 warps (256 threads), 3-stage cp.async pipeline.
// ---------------------------------------------------------------------------
template <int BN, int WARPS_M, int WARPS_N, bool A_FP32, bool OUT_FP32>
__global__ void __launch_bounds__(WARPS_M * WARPS_N * 32, 1)
mlp_gemm(const float* __restrict__ Xfp,
         const __nv_bfloat16* __restrict__ Ah,
         const __nv_bfloat16* __restrict__ Al, int lda,
         const __nv_bfloat16* __restrict__ Bh,
         const __nv_bfloat16* __restrict__ Bl, int ldb,
         const float* __restrict__ bias, int n_bias,
         __nv_bfloat16* __restrict__ Oh,
         __nv_bfloat16* __restrict__ Ol,
         float* __restrict__ Ofp, int ldo,
         int ktiles) {
    constexpr int THREADS = WARPS_M * WARPS_N * 32;
    constexpr int WM = MT / WARPS_M;   // warp M tile
    constexpr int WN = BN / WARPS_N;   // warp N tile
    constexpr int MF = WM / 16;        // m16 frags
    constexpr int NF = WN / 8;         // n8 frags
    constexpr int A_B = MT * 64;       // bytes per A buffer (hi or lo)
    constexpr int B_B = BN * 64;       // bytes per B buffer
    constexpr int STAGE = 2 * A_B + 2 * B_B;
    constexpr int NSTAGE = 3;

    extern __shared__ __align__(128) char smem[];
    float* sbias = reinterpret_cast<float*>(smem + NSTAGE * STAGE);
    const uint32_t sbase = smem_u32(smem);

    const int tid = threadIdx.x;
    const int wid = tid >> 5;
    const int lane = tid & 31;
    const int warp_m = wid % WARPS_M;
    const int warp_n = wid / WARPS_M;
    const int m0 = blockIdx.x * MT;
    const int n0 = blockIdx.y * BN;

    // bias -> smem
    for (int i = tid; i < BN; i += THREADS)
        sbias[i] = (n0 + i < n_bias) ? bias[n0 + i] : 0.0f;

    // ldmatrix lane geometry
    const int row_a = warp_m * WM + ((lane & 7) | (((lane >> 3) & 1) << 3));
    const int csel_a = lane >> 4;
    const int swz_a = (row_a >> 1) & 3;
    const int row_b = warp_n * WN + ((lane & 7) | (((lane >> 4) & 1) << 3));
    const int csel_b = (lane >> 3) & 1;
    const int swz_b = (row_b >> 1) & 3;

    float acc[MF][NF][4] = {};

    // pending fp32 X loads (layer-0 path)
    float4 px[2][2];
    uint32_t pdst[2];

    // ---------------- tile loaders ----------------
    auto load_B = [&](int kt, int s) {
        const uint32_t base = sbase + s * STAGE + 2 * A_B;
        #pragma unroll
        for (int it = 0; it < (2 * BN * 4) / THREADS; it++) {
            int g = it * THREADS + tid;
            int buf = (g >= BN * 4) ? 1 : 0;
            int w = g - buf * BN * 4;
            int r = w >> 2, c = w & 3;
            const __nv_bfloat16* src =
                (buf ? Bl : Bh) + (size_t)(n0 + r) * ldb + kt * BK + c * 8;
            cp16(base + buf * B_B + tile_off(r, c), src);
        }
    };
    auto load_A_bf16 = [&](int kt, int s) {
        const uint32_t base = sbase + s * STAGE;
        #pragma unroll
        for (int it = 0; it < (2 * MT * 4) / THREADS; it++) {
            int g = it * THREADS + tid;
            int buf = (g >= MT * 4) ? 1 : 0;
            int w = g - buf * MT * 4;
            int r = w >> 2, c = w & 3;
            const __nv_bfloat16* src =
                (buf ? Al : Ah) + (size_t)(m0 + r) * lda + kt * BK + c * 8;
            cp16(base + buf * A_B + tile_off(r, c), src);
        }
    };
    auto ldg_A_fp32 = [&](int kt) {
        #pragma unroll
        for (int it = 0; it < 2; it++) {
            int g = it * THREADS + tid;
            int r = g >> 2, c = g & 3;
            int k0 = kt * BK + c * 8;
            bool valid = (m0 + r < M_REAL) && (k0 < IN_DIM);
            float4 z = make_float4(0.f, 0.f, 0.f, 0.f);
            if (valid) {
                const float4* p =
                    reinterpret_cast<const float4*>(Xfp + (size_t)(m0 + r) * lda + k0);
                px[it][0] = p[0];
                px[it][1] = p[1];
            } else {
                px[it][0] = z;
                px[it][1] = z;
            }
            pdst[it] = tile_off(r, c);
        }
    };
    auto sts_A_fp32 = [&](int s) {
        char* base = smem + s * STAGE;
        #pragma unroll
        for (int it = 0; it < 2; it++) {
            float f[8] = {px[it][0].x, px[it][0].y, px[it][0].z, px[it][0].w,
                          px[it][1].x, px[it][1].y, px[it][1].z, px[it][1].w};
            uint32_t hw[4], lw[4];
            #pragma unroll
            for (int i = 0; i < 4; i++) {
                __nv_bfloat16 h0, l0, h1, l1;
                split1(f[2 * i], h0, l0);
                split1(f[2 * i + 1], h1, l1);
                hw[i] = pack_bf2(h0, h1);
                lw[i] = pack_bf2(l0, l1);
            }
            *reinterpret_cast<uint4*>(base + pdst[it]) =
                make_uint4(hw[0], hw[1], hw[2], hw[3]);
            *reinterpret_cast<uint4*>(base + A_B + pdst[it]) =
                make_uint4(lw[0], lw[1], lw[2], lw[3]);
        }
    };

    // ---------------- prologue: stages 0,1 ----------------
    load_B(0, 0);
    if constexpr (A_FP32) { ldg_A_fp32(0); sts_A_fp32(0); }
    else                  { load_A_bf16(0, 0); }
    asm volatile("cp.async.commit_group;" ::: "memory");
    load_B(1, 1);
    if constexpr (A_FP32) { ldg_A_fp32(1); sts_A_fp32(1); }
    else                  { load_A_bf16(1, 1); }
    asm volatile("cp.async.commit_group;" ::: "memory");

    // ---------------- main loop ----------------
    for (int kt = 0; kt < ktiles; kt++) {
        const int s = kt % NSTAGE;
        asm volatile("cp.async.wait_group 1;" ::: "memory");
        __syncthreads();

        const int nk = kt + 2;
        const bool pre = nk < ktiles;
        const int sn = nk % NSTAGE;
        if (pre) {
            load_B(nk, sn);
            if constexpr (A_FP32) ldg_A_fp32(nk);
            else                  load_A_bf16(nk, sn);
        }

        // ---- compute stage s ----
        const uint32_t sa = sbase + s * STAGE;
        const uint32_t sb = sa + 2 * A_B;
        #pragma unroll
        for (int ks = 0; ks < 2; ks++) {
            const uint32_t aoff = (uint32_t)row_a * 64 +
                                  (uint32_t)(((ks * 2 + csel_a) ^ swz_a) << 4);
            const uint32_t boff = (uint32_t)row_b * 64 +
                                  (uint32_t)(((ks * 2 + csel_b) ^ swz_b) << 4);
            uint32_t ah[MF][4], bb[NF][2];
            #pragma unroll
            for (int mf = 0; mf < MF; mf++)
                ldsm4(sa + aoff + mf * 1024, ah[mf][0], ah[mf][1], ah[mf][2], ah[mf][3]);
            #pragma unroll
            for (int nf2 = 0; nf2 < NF / 2; nf2++) {
                uint32_t r0, r1, r2, r3;
                ldsm4(sb + boff + nf2 * 1024, r0, r1, r2, r3);
                bb[2 * nf2][0] = r0; bb[2 * nf2][1] = r1;
                bb[2 * nf2 + 1][0] = r2; bb[2 * nf2 + 1][1] = r3;
            }
            // pass 1: Ah * Bh
            #pragma unroll
            for (int mf = 0; mf < MF; mf++)
                #pragma unroll
                for (int nf = 0; nf < NF; nf++)
                    mma16816(acc[mf][nf], ah[mf], bb[nf]);
            // pass 2: Al * Bh
            uint32_t al[MF][4];
            #pragma unroll
            for (int mf = 0; mf < MF; mf++)
                ldsm4(sa + A_B + aoff + mf * 1024, al[mf][0], al[mf][1], al[mf][2], al[mf][3]);
            #pragma unroll
            for (int mf = 0; mf < MF; mf++)
                #pragma unroll
                for (int nf = 0; nf < NF; nf++)
                    mma16816(acc[mf][nf], al[mf], bb[nf]);
            // pass 3: Ah * Bl  (reuse bb regs)
            #pragma unroll
            for (int nf2 = 0; nf2 < NF / 2; nf2++) {
                uint32_t r0, r1, r2, r3;
                ldsm4(sb + B_B + boff + nf2 * 1024, r0, r1, r2, r3);
                bb[2 * nf2][0] = r0; bb[2 * nf2][1] = r1;
                bb[2 * nf2 + 1][0] = r2; bb[2 * nf2 + 1][1] = r3;
            }
            #pragma unroll
            for (int mf = 0; mf < MF; mf++)
                #pragma unroll
                for (int nf = 0; nf < NF; nf++)
                    mma16816(acc[mf][nf], ah[mf], bb[nf]);
        }

        if (pre) { if constexpr (A_FP32) sts_A_fp32(sn); }
        asm volatile("cp.async.commit_group;" ::: "memory");
    }

    // ---------------- epilogue: bias + ReLU + store ----------------
    const int gid = lane >> 2;   // accum row group 0..7
    const int tig = lane & 3;    // accum col group
    #pragma unroll
    for (int mf = 0; mf < MF; mf++) {
        #pragma unroll
        for (int nf = 0; nf < NF; nf++) {
            const int col0 = warp_n * WN + nf * 8 + tig * 2;
            const float bv0 = sbias[col0], bv1 = sbias[col0 + 1];
            #pragma unroll
            for (int half = 0; half < 2; half++) {
                const int m = m0 + warp_m * WM + mf * 16 + gid + half * 8;
                float v0 = fmaxf(acc[mf][nf][2 * half + 0] + bv0, 0.0f);
                float v1 = fmaxf(acc[mf][nf][2 * half + 1] + bv1, 0.0f);
                if (m < M_REAL) {
                    if constexpr (OUT_FP32) {
                        if (col0 < LAT)     Ofp[(size_t)m * ldo + col0]     = v0;
                        if (col0 + 1 < LAT) Ofp[(size_t)m * ldo + col0 + 1] = v1;
                    } else {
                        __nv_bfloat16 h0, l0, h1, l1;
                        split1(v0, h0, l0);
                        split1(v1, h1, l1);
                        const size_t idx = (size_t)m * ldo + n0 + col0;
                        *reinterpret_cast<uint32_t*>(Oh + idx) = pack_bf2(h0, h1);
                        *reinterpret_cast<uint32_t*>(Ol + idx) = pack_bf2(l0, l1);
                    }
                }
            }
        }
    }
}

// ---------------------------------------------------------------------------
// Host launch
// ---------------------------------------------------------------------------
extern "C" void kernel_launch(void* const* d_in, const int* in_sizes, int n_in,
                              void* d_out, int out_size) {
    const float* X  = (const float*)d_in[0];
    // d_in[1] = g (dead)
    const float* W0 = (const float*)d_in[2];
    const float* b0 = (const float*)d_in[3];
    const float* W1 = (const float*)d_in[4];
    const float* b1 = (const float*)d_in[5];
    const float* W2 = (const float*)d_in[6];
    const float* b2 = (const float*)d_in[7];
    const float* W3 = (const float*)d_in[8];
    const float* b3 = (const float*)d_in[9];
    float* out = (float*)d_out;

    void *w0h, *w0l, *w1h, *w1l, *w2h, *w2l, *w3h, *w3l, *hah, *hal, *hbh, *hbl;
    cudaGetSymbolAddress(&w0h, g_W0h); cudaGetSymbolAddress(&w0l, g_W0l);
    cudaGetSymbolAddress(&w1h, g_W1h); cudaGetSymbolAddress(&w1l, g_W1l);
    cudaGetSymbolAddress(&w2h, g_W2h); cudaGetSymbolAddress(&w2l, g_W2l);
    cudaGetSymbolAddress(&w3h, g_W3h); cudaGetSymbolAddress(&w3l, g_W3l);
    cudaGetSymbolAddress(&hah, g_Hah); cudaGetSymbolAddress(&hal, g_Hal);
    cudaGetSymbolAddress(&hbh, g_Hbh); cudaGetSymbolAddress(&hbl, g_Hbl);

    // weight prep
    prep_w<<<(HID * IN_PAD + 255) / 256, 256>>>(
        W0, (__nv_bfloat16*)w0h, (__nv_bfloat16*)w0l, IN_DIM, HID, IN_PAD, HID);
    prep_w<<<(HID * HID + 255) / 256, 256>>>(
        W1, (__nv_bfloat16*)w1h, (__nv_bfloat16*)w1l, HID, HID, HID, HID);
    prep_w<<<(HID * HID + 255) / 256, 256>>>(
        W2, (__nv_bfloat16*)w2h, (__nv_bfloat16*)w2l, HID, HID, HID, HID);
    prep_w<<<(32 * HID + 255) / 256, 256>>>(
        W3, (__nv_bfloat16*)w3h, (__nv_bfloat16*)w3l, HID, LAT, HID, 32);

    const int mtiles = (M_REAL + MT - 1) / MT;  // 782

    // smem: 3 stages + bias
    constexpr int SM256 = 3 * (2 * MT * 64 + 2 * 256 * 64) + 256 * 4;  // 148480
    constexpr int SM32  = 3 * (2 * MT * 64 + 2 * 32 * 64) + 32 * 4;    // 61568

    cudaFuncSetAttribute((const void*)mlp_gemm<256, 2, 4, true, false>,
                         cudaFuncAttributeMaxDynamicSharedMemorySize, SM256);
    cudaFuncSetAttribute((const void*)mlp_gemm<256, 2, 4, false, false>,
                         cudaFuncAttributeMaxDynamicSharedMemorySize, SM256);
    cudaFuncSetAttribute((const void*)mlp_gemm<32, 4, 2, false, true>,
                         cudaFuncAttributeMaxDynamicSharedMemorySize, SM32);

    // layer 0: X fp32 -> Ha (split bf16), K = 3008, N passes = 2
    mlp_gemm<256, 2, 4, true, false><<<dim3(mtiles, 2), 256, SM256>>>(
        X, nullptr, nullptr, IN_DIM,
        (const __nv_bfloat16*)w0h, (const __nv_bfloat16*)w0l, IN_PAD,
        b0, HID,
        (__nv_bfloat16*)hah, (__nv_bfloat16*)hal, nullptr, HID, IN_PAD / BK);

    // layer 1: Ha -> Hb
    mlp_gemm<256, 2, 4, false, false><<<dim3(mtiles, 2), 256, SM256>>>(
        nullptr, (const __nv_bfloat16*)hah, (const __nv_bfloat16*)hal, HID,
        (const __nv_bfloat16*)w1h, (const __nv_bfloat16*)w1l, HID,
        b1, HID,
        (__nv_bfloat16*)hbh, (__nv_bfloat16*)hbl, nullptr, HID, HID / BK);

    // layer 2: Hb -> Ha
    mlp_gemm<256, 2, 4, false, false><<<dim3(mtiles, 2), 256, SM256>>>(
        nullptr, (const __nv_bfloat16*)hbh, (const __nv_bfloat16*)hbl, HID,
        (const __nv_bfloat16*)w2h, (const __nv_bfloat16*)w2l, HID,
        b2, HID,
        (__nv_bfloat16*)hah, (__nv_bfloat16*)hal, nullptr, HID, HID / BK);

    // layer 3: Ha -> out fp32 [100000, 20]
    mlp_gemm<32, 4, 2, false, true><<<dim3(mtiles, 1), 256, SM32>>>(
        nullptr, (const __nv_bfloat16*)hah, (const __nv_bfloat16*)hal, HID,
        (const __nv_bfloat16*)w3h, (const __nv_bfloat16*)w3l, HID,
        b3, LAT,
        nullptr, nullptr, out, LAT, HID / BK);

    (void)in_sizes; (void)n_in; (void)out_size;
}

// round 5
// speedup vs baseline: 1.3363x; 1.3363x over previous
#include <cuda_runtime.h>
#include <cuda_fp16.h>
#include <cstdint>
#include <cstddef>

// ---------------------------------------------------------------------------
// Problem constants
// ---------------------------------------------------------------------------
static constexpr int IN_DIM  = 3000;
static constexpr int IN_PAD  = 3008;    // K padded to multiple of 64
static constexpr int HID     = 512;
static constexpr int LAT     = 20;
static constexpr int M_REAL  = 100000;
static constexpr int M_PAD   = 100096;  // 782 * 128
static constexpr int MT      = 128;     // CTA M tile

// ---------------------------------------------------------------------------
// Static device scratch (allocation-free rule)
// Weights transposed to [N][K_pad] fp16 hi/lo, zero padded.
// Hidden activations as fp16 hi/lo pairs, rows padded to M_PAD (zero-init .bss:
// rows >= M_REAL are never written and stay 0).
// ---------------------------------------------------------------------------
__device__ __align__(16) __half g_W0h[HID * IN_PAD];
__device__ __align__(16) __half g_W0l[HID * IN_PAD];   // unused by 2-pass L0, kept for safety/testing
__device__ __align__(16) __half g_W1h[HID * HID];
__device__ __align__(16) __half g_W1l[HID * HID];
__device__ __align__(16) __half g_W2h[HID * HID];
__device__ __align__(16) __half g_W2l[HID * HID];
__device__ __align__(16) __half g_W3h[32 * HID];
__device__ __align__(16) __half g_W3l[32 * HID];
__device__ __align__(16) __half g_Hah[(size_t)M_PAD * HID];
__device__ __align__(16) __half g_Hal[(size_t)M_PAD * HID];
__device__ __align__(16) __half g_Hbh[(size_t)M_PAD * HID];
__device__ __align__(16) __half g_Hbl[(size_t)M_PAD * HID];

// ---------------------------------------------------------------------------
// Helpers
// ---------------------------------------------------------------------------
__device__ __forceinline__ uint32_t smem_u32(const void* p) {
    uint32_t a;
    asm("{ .reg .u64 t; cvta.to.shared.u64 t, %1; cvt.u32.u64 %0, t; }"
        : "=r"(a) : "l"(p));
    return a;
}

__device__ __forceinline__ void cp16(uint32_t dst, const void* src) {
    asm volatile("cp.async.cg.shared.global [%0], [%1], 16;"
                 :: "r"(dst), "l"(src) : "memory");
}

__device__ __forceinline__ void ldsm4(uint32_t addr, uint32_t& r0, uint32_t& r1,
                                      uint32_t& r2, uint32_t& r3) {
    asm volatile("ldmatrix.sync.aligned.m8n8.x4.shared.b16 {%0,%1,%2,%3}, [%4];"
                 : "=r"(r0), "=r"(r1), "=r"(r2), "=r"(r3) : "r"(addr));
}

__device__ __forceinline__ void mma16816(float* c, const uint32_t* a, const uint32_t* b) {
    asm volatile(
        "mma.sync.aligned.m16n8k16.row.col.f32.f16.f16.f32 "
        "{%0,%1,%2,%3}, {%4,%5,%6,%7}, {%8,%9}, {%0,%1,%2,%3};"
        : "+f"(c[0]), "+f"(c[1]), "+f"(c[2]), "+f"(c[3])
        : "r"(a[0]), "r"(a[1]), "r"(a[2]), "r"(a[3]), "r"(b[0]), "r"(b[1]));
}

__device__ __forceinline__ void split1(float v, __half& h, __half& l) {
    h = __float2half(v);
    l = __float2half(v - __half2float(h));
}

__device__ __forceinline__ uint32_t pack_h2(__half a, __half b) {
    __half2 t = __halves2half2(a, b);  // .x = a (low half)
    return *reinterpret_cast<uint32_t*>(&t);
}

// ---------------------------------------------------------------------------
// Fused weight prep (one launch): W[K][N] fp32 -> Wt[N_pad][K_pad] fp16 hi/lo
// ---------------------------------------------------------------------------
__device__ __forceinline__ void prep_one(const float* W, __half* dh, __half* dl,
                                         int K, int N, int K_pad, int idx) {
    int n = idx / K_pad, k = idx - n * K_pad;
    float v = (n < N && k < K) ? W[(size_t)k * N + n] : 0.0f;
    __half h, l;
    split1(v, h, l);
    dh[idx] = h;
    dl[idx] = l;
}

__global__ void prep_all(const float* W0, const float* W1, const float* W2,
                         const float* W3,
                         __half* w0h, __half* w0l, __half* w1h, __half* w1l,
                         __half* w2h, __half* w2l, __half* w3h, __half* w3l) {
    constexpr int B0 = HID * IN_PAD / 256;       // 6016
    constexpr int B1 = B0 + HID * HID / 256;     // 7040
    constexpr int B2 = B1 + HID * HID / 256;     // 8064
    int b = blockIdx.x;
    int t = threadIdx.x;
    if (b < B0) {
        prep_one(W0, w0h, w0l, IN_DIM, HID, IN_PAD, b * 256 + t);
    } else if (b < B1) {
        prep_one(W1, w1h, w1l, HID, HID, HID, (b - B0) * 256 + t);
    } else if (b < B2) {
        prep_one(W2, w2h, w2l, HID, HID, HID, (b - B1) * 256 + t);
    } else {
        prep_one(W3, w3h, w3l, HID, LAT, HID, (b - B2) * 256 + t);
    }
}

// ---------------------------------------------------------------------------
// Split-fp16 GEMM + bias + ReLU via mma.sync m16n8k16
//   NPASS==2: D = Ah*B + Al*B          (A exact, B single fp16)
//   NPASS==3: D = Ah*Bh + Al*Bh + Ah*Bl
// 8 warps (256 threads), NSTAGE=3 cp.async pipeline.
// ---------------------------------------------------------------------------
template <int BN, int BK, int WARPS_M, int WARPS_N, int NPASS,
          bool A_FP32, bool OUT_FP32>
__global__ void __launch_bounds__(WARPS_M * WARPS_N * 32, 1)
mlp_gemm(const float* __restrict__ Xfp,
         const __half* __restrict__ Ah,
         const __half* __restrict__ Al, int lda,
         const __half* __restrict__ Bh,
         const __half* __restrict__ Bl, int ldb,
         const float* __restrict__ bias, int n_bias,
         __half* __restrict__ Oh,
         __half* __restrict__ Ol,
         float* __restrict__ Ofp, int ldo,
         int ktiles) {
    constexpr int THREADS = WARPS_M * WARPS_N * 32;
    constexpr int WM = MT / WARPS_M;
    constexpr int WN = BN / WARPS_N;
    constexpr int MF = WM / 16;
    constexpr int NF = WN / 8;
    constexpr int CPR = BK / 8;            // 16B chunks per row
    constexpr int ROWB = 2 * BK;           // row bytes
    constexpr int SWS = (BK == 64) ? 0 : 1;
    constexpr int NBBUF = (NPASS == 3) ? 2 : 1;
    constexpr int A_B = MT * ROWB;
    constexpr int B_B = BN * ROWB;
    constexpr int STAGE = 2 * A_B + NBBUF * B_B;
    constexpr int NSTAGE = 3;
    constexpr int KS_PER = BK / 16;

    extern __shared__ __align__(128) char smem[];
    float* sbias = reinterpret_cast<float*>(smem + NSTAGE * STAGE);
    const uint32_t sbase = smem_u32(smem);

    const int tid = threadIdx.x;
    const int wid = tid >> 5;
    const int lane = tid & 31;
    const int warp_m = wid % WARPS_M;
    const int warp_n = wid / WARPS_M;
    const int m0 = blockIdx.x * MT;
    const int n0 = blockIdx.y * BN;

    for (int i = tid; i < BN; i += THREADS)
        sbias[i] = (n0 + i < n_bias) ? bias[n0 + i] : 0.0f;

    auto toff = [](int r, int c) -> uint32_t {
        return (uint32_t)(r * ROWB + (((c ^ ((r >> SWS) & (CPR - 1)))) << 4));
    };

    // ldmatrix lane geometry (validated in round 3)
    const int row_a = warp_m * WM + ((lane & 7) | (((lane >> 3) & 1) << 3));
    const int csel_a = lane >> 4;
    const int swz_a = (row_a >> SWS) & (CPR - 1);
    const int row_b = warp_n * WN + ((lane & 7) | (((lane >> 4) & 1) << 3));
    const int csel_b = (lane >> 3) & 1;
    const int swz_b = (row_b >> SWS) & (CPR - 1);

    float acc[MF][NF][4] = {};

    // pending fp32 X loads (layer-0 path): groups of 8 floats
    constexpr int NPX = A_FP32 ? (MT * CPR / THREADS) : 1;
    float4 px[NPX][2];
    uint32_t pdst[NPX];

    // ---------------- tile loaders ----------------
    auto load_B = [&](int kt, int s) {
        const uint32_t base = sbase + s * STAGE + 2 * A_B;
        #pragma unroll
        for (int it = 0; it < (NBBUF * BN * CPR) / THREADS; it++) {
            int g = it * THREADS + tid;
            int buf = g / (BN * CPR);
            int w = g - buf * (BN * CPR);
            int r = w / CPR, c = w - r * CPR;
            const __half* src =
                (buf ? Bl : Bh) + (size_t)(n0 + r) * ldb + kt * BK + c * 8;
            cp16(base + buf * B_B + toff(r, c), src);
        }
    };
    auto load_A_f16 = [&](int kt, int s) {
        const uint32_t base = sbase + s * STAGE;
        #pragma unroll
        for (int it = 0; it < (2 * MT * CPR) / THREADS; it++) {
            int g = it * THREADS + tid;
            int buf = g / (MT * CPR);
            int w = g - buf * (MT * CPR);
            int r = w / CPR, c = w - r * CPR;
            const __half* src =
                (buf ? Al : Ah) + (size_t)(m0 + r) * lda + kt * BK + c * 8;
            cp16(base + buf * A_B + toff(r, c), src);
        }
    };
    auto ldg_A_fp32 = [&](int kt) {
        #pragma unroll
        for (int it = 0; it < NPX; it++) {
            int g = it * THREADS + tid;
            int r = g / CPR, c = g - r * CPR;
            int k0 = kt * BK + c * 8;
            float4 z = make_float4(0.f, 0.f, 0.f, 0.f);
            if ((m0 + r < M_REAL) && (k0 < IN_DIM)) {
                const float4* p =
                    reinterpret_cast<const float4*>(Xfp + (size_t)(m0 + r) * lda + k0);
                px[it][0] = p[0];
                px[it][1] = p[1];
            } else {
                px[it][0] = z;
                px[it][1] = z;
            }
            pdst[it] = toff(r, c);
        }
    };
    auto sts_A_fp32 = [&](int s) {
        char* base = smem + s * STAGE;
        #pragma unroll
        for (int it = 0; it < NPX; it++) {
            float f[8] = {px[it][0].x, px[it][0].y, px[it][0].z, px[it][0].w,
                          px[it][1].x, px[it][1].y, px[it][1].z, px[it][1].w};
            uint32_t hw[4], lw[4];
            #pragma unroll
            for (int i = 0; i < 4; i++) {
                __half h0, l0, h1, l1;
                split1(f[2 * i], h0, l0);
                split1(f[2 * i + 1], h1, l1);
                hw[i] = pack_h2(h0, h1);
                lw[i] = pack_h2(l0, l1);
            }
            *reinterpret_cast<uint4*>(base + pdst[it]) =
                make_uint4(hw[0], hw[1], hw[2], hw[3]);
            *reinterpret_cast<uint4*>(base + A_B + pdst[it]) =
                make_uint4(lw[0], lw[1], lw[2], lw[3]);
        }
    };

    // ---------------- prologue: stages 0,1 ----------------
    load_B(0, 0);
    if constexpr (A_FP32) { ldg_A_fp32(0); sts_A_fp32(0); }
    else                  { load_A_f16(0, 0); }
    asm volatile("cp.async.commit_group;" ::: "memory");
    load_B(1, 1);
    if constexpr (A_FP32) { ldg_A_fp32(1); sts_A_fp32(1); }
    else                  { load_A_f16(1, 1); }
    asm volatile("cp.async.commit_group;" ::: "memory");

    // ---------------- main loop ----------------
    for (int kt = 0; kt < ktiles; kt++) {
        const int s = kt % NSTAGE;
        asm volatile("cp.async.wait_group 1;" ::: "memory");
        __syncthreads();

        const int nk = kt + 2;
        const bool pre = nk < ktiles;
        const int sn = nk % NSTAGE;
        if (pre) {
            load_B(nk, sn);
            if constexpr (A_FP32) ldg_A_fp32(nk);
            else                  load_A_f16(nk, sn);
        }

        // ---- compute stage s ----
        const uint32_t sa = sbase + s * STAGE;
        const uint32_t sb = sa + 2 * A_B;
        #pragma unroll
        for (int ks = 0; ks < KS_PER; ks++) {
            const uint32_t aoff = (uint32_t)row_a * ROWB +
                                  (uint32_t)(((ks * 2 + csel_a) ^ swz_a) << 4);
            const uint32_t boff = (uint32_t)row_b * ROWB +
                                  (uint32_t)(((ks * 2 + csel_b) ^ swz_b) << 4);
            uint32_t ah[MF][4], bb[NF][2];
            #pragma unroll
            for (int mf = 0; mf < MF; mf++)
                ldsm4(sa + aoff + mf * 16 * ROWB,
                      ah[mf][0], ah[mf][1], ah[mf][2], ah[mf][3]);
            #pragma unroll
            for (int nf2 = 0; nf2 < NF / 2; nf2++) {
                uint32_t r0, r1, r2, r3;
                ldsm4(sb + boff + nf2 * 16 * ROWB, r0, r1, r2, r3);
                bb[2 * nf2][0] = r0; bb[2 * nf2][1] = r1;
                bb[2 * nf2 + 1][0] = r2; bb[2 * nf2 + 1][1] = r3;
            }
            // pass 1: Ah * B(h)
            #pragma unroll
            for (int mf = 0; mf < MF; mf++)
                #pragma unroll
                for (int nf = 0; nf < NF; nf++)
                    mma16816(acc[mf][nf], ah[mf], bb[nf]);
            // pass 2: Al * B(h)
            uint32_t al[MF][4];
            #pragma unroll
            for (int mf = 0; mf < MF; mf++)
                ldsm4(sa + A_B + aoff + mf * 16 * ROWB,
                      al[mf][0], al[mf][1], al[mf][2], al[mf][3]);
            #pragma unroll
            for (int mf = 0; mf < MF; mf++)
                #pragma unroll
                for (int nf = 0; nf < NF; nf++)
                    mma16816(acc[mf][nf], al[mf], bb[nf]);
            // pass 3: Ah * Bl
            if constexpr (NPASS == 3) {
                #pragma unroll
                for (int nf2 = 0; nf2 < NF / 2; nf2++) {
                    uint32_t r0, r1, r2, r3;
                    ldsm4(sb + B_B + boff + nf2 * 16 * ROWB, r0, r1, r2, r3);
                    bb[2 * nf2][0] = r0; bb[2 * nf2][1] = r1;
                    bb[2 * nf2 + 1][0] = r2; bb[2 * nf2 + 1][1] = r3;
                }
                #pragma unroll
                for (int mf = 0; mf < MF; mf++)
                    #pragma unroll
                    for (int nf = 0; nf < NF; nf++)
                        mma16816(acc[mf][nf], ah[mf], bb[nf]);
            }
        }

        if (pre) { if constexpr (A_FP32) sts_A_fp32(sn); }
        asm volatile("cp.async.commit_group;" ::: "memory");
    }

    // ---------------- epilogue: bias + ReLU + store ----------------
    const int gid = lane >> 2;
    const int tig = lane & 3;
    #pragma unroll
    for (int mf = 0; mf < MF; mf++) {
        #pragma unroll
        for (int nf = 0; nf < NF; nf++) {
            const int col0 = warp_n * WN + nf * 8 + tig * 2;
            const float bv0 = sbias[col0], bv1 = sbias[col0 + 1];
            #pragma unroll
            for (int half = 0; half < 2; half++) {
                const int m = m0 + warp_m * WM + mf * 16 + gid + half * 8;
                float v0 = fmaxf(acc[mf][nf][2 * half + 0] + bv0, 0.0f);
                float v1 = fmaxf(acc[mf][nf][2 * half + 1] + bv1, 0.0f);
                if (m < M_REAL) {
                    if constexpr (OUT_FP32) {
                        if (col0 < LAT)     Ofp[(size_t)m * ldo + col0]     = v0;
                        if (col0 + 1 < LAT) Ofp[(size_t)m * ldo + col0 + 1] = v1;
                    } else {
                        __half h0, l0, h1, l1;
                        split1(v0, h0, l0);
                        split1(v1, h1, l1);
                        const size_t idx = (size_t)m * ldo + n0 + col0;
                        *reinterpret_cast<uint32_t*>(Oh + idx) = pack_h2(h0, h1);
                        *reinterpret_cast<uint32_t*>(Ol + idx) = pack_h2(l0, l1);
                    }
                }
            }
        }
    }
}

// ---------------------------------------------------------------------------
// Host launch
// ---------------------------------------------------------------------------
extern "C" void kernel_launch(void* const* d_in, const int* in_sizes, int n_in,
                              void* d_out, int out_size) {
    const float* X  = (const float*)d_in[0];
    // d_in[1] = g (dead)
    const float* W0 = (const float*)d_in[2];
    const float* b0 = (const float*)d_in[3];
    const float* W1 = (const float*)d_in[4];
    const float* b1 = (const float*)d_in[5];
    const float* W2 = (const float*)d_in[6];
    const float* b2 = (const float*)d_in[7];
    const float* W3 = (const float*)d_in[8];
    const float* b3 = (const float*)d_in[9];
    float* out = (float*)d_out;

    void *w0h, *w0l, *w1h, *w1l, *w2h, *w2l, *w3h, *w3l, *hah, *hal, *hbh, *hbl;
    cudaGetSymbolAddress(&w0h, g_W0h); cudaGetSymbolAddress(&w0l, g_W0l);
    cudaGetSymbolAddress(&w1h, g_W1h); cudaGetSymbolAddress(&w1l, g_W1l);
    cudaGetSymbolAddress(&w2h, g_W2h); cudaGetSymbolAddress(&w2l, g_W2l);
    cudaGetSymbolAddress(&w3h, g_W3h); cudaGetSymbolAddress(&w3l, g_W3l);
    cudaGetSymbolAddress(&hah, g_Hah); cudaGetSymbolAddress(&hal, g_Hal);
    cudaGetSymbolAddress(&hbh, g_Hbh); cudaGetSymbolAddress(&hbl, g_Hbl);

    // single fused weight-prep launch
    constexpr int PREP_BLOCKS =
        HID * IN_PAD / 256 + HID * HID / 256 + HID * HID / 256 + 32 * HID / 256;
    prep_all<<<PREP_BLOCKS, 256>>>(
        W0, W1, W2, W3,
        (__half*)w0h, (__half*)w0l, (__half*)w1h, (__half*)w1l,
        (__half*)w2h, (__half*)w2l, (__half*)w3h, (__half*)w3l);

    const int mtiles = (M_REAL + MT - 1) / MT;  // 782

    // smem sizes (3 stages + bias)
    constexpr int SM_L0 = 3 * (2 * MT * 128 + 1 * 256 * 128) + 256 * 4;  // 197632
    constexpr int SM_L12 = 3 * (2 * MT * 64 + 2 * 256 * 64) + 256 * 4;   // 148480
    constexpr int SM_L3 = 3 * (2 * MT * 64 + 2 * 32 * 64) + 32 * 4;      // 61568

    cudaFuncSetAttribute((const void*)mlp_gemm<256, 64, 2, 4, 2, true, false>,
                         cudaFuncAttributeMaxDynamicSharedMemorySize, SM_L0);
    cudaFuncSetAttribute((const void*)mlp_gemm<256, 32, 2, 4, 3, false, false>,
                         cudaFuncAttributeMaxDynamicSharedMemorySize, SM_L12);
    cudaFuncSetAttribute((const void*)mlp_gemm<32, 32, 4, 2, 3, false, true>,
                         cudaFuncAttributeMaxDynamicSharedMemorySize, SM_L3);

    // layer 0: X fp32 (split inline, exact) x W0 (single fp16), 2-pass, BK=64
    mlp_gemm<256, 64, 2, 4, 2, true, false><<<dim3(mtiles, 2), 256, SM_L0>>>(
        X, nullptr, nullptr, IN_DIM,
        (const __half*)w0h, (const __half*)w0l, IN_PAD,
        b0, HID,
        (__half*)hah, (__half*)hal, nullptr, HID, IN_PAD / 64);

    // layer 1: Ha (split) x W1 (split), 3-pass
    mlp_gemm<256, 32, 2, 4, 3, false, false><<<dim3(mtiles, 2), 256, SM_L12>>>(
        nullptr, (const __half*)hah, (const __half*)hal, HID,
        (const __half*)w1h, (const __half*)w1l, HID,
        b1, HID,
        (__half*)hbh, (__half*)hbl, nullptr, HID, HID / 32);

    // layer 2: Hb -> Ha, 3-pass
    mlp_gemm<256, 32, 2, 4, 3, false, false><<<dim3(mtiles, 2), 256, SM_L12>>>(
        nullptr, (const __half*)hbh, (const __half*)hbl, HID,
        (const __half*)w2h, (const __half*)w2l, HID,
        b2, HID,
        (__half*)hah, (__half*)hal, nullptr, HID, HID / 32);

    // layer 3: Ha -> out fp32 [100000, 20], 3-pass
    mlp_gemm<32, 32, 4, 2, 3, false, true><<<dim3(mtiles, 1), 256, SM_L3>>>(
        nullptr, (const __half*)hah, (const __half*)hal, HID,
        (const __half*)w3h, (const __half*)w3l, HID,
        b3, LAT,
        nullptr, nullptr, out, LAT, HID / 32);

    (void)in_sizes; (void)n_in; (void)out_size;
}

// round 7
// speedup vs baseline: 1.5247x; 1.1409x over previous
#include <cuda_runtime.h>
#include <cuda_fp16.h>
#include <cstdint>
#include <cstddef>

// ---------------------------------------------------------------------------
// Problem constants
// ---------------------------------------------------------------------------
static constexpr int IN_DIM  = 3000;
static constexpr int IN_PAD  = 3008;    // K padded to multiple of 64
static constexpr int HID     = 512;
static constexpr int LAT     = 20;
static constexpr int M_REAL  = 100000;
static constexpr int M_PAD   = 100096;  // 782 * 128
static constexpr int MT      = 128;     // CTA M tile

// ---------------------------------------------------------------------------
// Static device scratch (allocation-free rule)
// Weights transposed to [N][K_pad] fp16 hi/lo, zero padded.
// Hidden activations as fp16 hi/lo pairs, rows padded to M_PAD.
// ---------------------------------------------------------------------------
__device__ __align__(16) __half g_W0h[HID * IN_PAD];
__device__ __align__(16) __half g_W0l[HID * IN_PAD];   // computed, unused (2-pass)
__device__ __align__(16) __half g_W1h[HID * HID];
__device__ __align__(16) __half g_W1l[HID * HID];
__device__ __align__(16) __half g_W2h[HID * HID];
__device__ __align__(16) __half g_W2l[HID * HID];
__device__ __align__(16) __half g_W3h[32 * HID];
__device__ __align__(16) __half g_W3l[32 * HID];
__device__ __align__(16) __half g_Hah[(size_t)M_PAD * HID];
__device__ __align__(16) __half g_Hal[(size_t)M_PAD * HID];
__device__ __align__(16) __half g_Hbh[(size_t)M_PAD * HID];
__device__ __align__(16) __half g_Hbl[(size_t)M_PAD * HID];

// ---------------------------------------------------------------------------
// Helpers
// ---------------------------------------------------------------------------
__device__ __forceinline__ uint32_t smem_u32(const void* p) {
    uint32_t a;
    asm("{ .reg .u64 t; cvta.to.shared.u64 t, %1; cvt.u32.u64 %0, t; }"
        : "=r"(a) : "l"(p));
    return a;
}

__device__ __forceinline__ void cp16(uint32_t dst, const void* src) {
    asm volatile("cp.async.cg.shared.global [%0], [%1], 16;"
                 :: "r"(dst), "l"(src) : "memory");
}

__device__ __forceinline__ void ldsm4(uint32_t addr, uint32_t& r0, uint32_t& r1,
                                      uint32_t& r2, uint32_t& r3) {
    asm volatile("ldmatrix.sync.aligned.m8n8.x4.shared.b16 {%0,%1,%2,%3}, [%4];"
                 : "=r"(r0), "=r"(r1), "=r"(r2), "=r"(r3) : "r"(addr));
}

__device__ __forceinline__ void mma16816(float* c, const uint32_t* a, const uint32_t* b) {
    asm volatile(
        "mma.sync.aligned.m16n8k16.row.col.f32.f16.f16.f32 "
        "{%0,%1,%2,%3}, {%4,%5,%6,%7}, {%8,%9}, {%0,%1,%2,%3};"
        : "+f"(c[0]), "+f"(c[1]), "+f"(c[2]), "+f"(c[3])
        : "r"(a[0]), "r"(a[1]), "r"(a[2]), "r"(a[3]), "r"(b[0]), "r"(b[1]));
}

__device__ __forceinline__ void split1(float v, __half& h, __half& l) {
    h = __float2half(v);
    l = __float2half(v - __half2float(h));
}

__device__ __forceinline__ uint32_t pack_h2(__half a, __half b) {
    __half2 t = __halves2half2(a, b);  // .x = a (low half)
    return *reinterpret_cast<uint32_t*>(&t);
}

// ---------------------------------------------------------------------------
// Fused weight prep (one launch): W[K][N] fp32 -> Wt[N_pad][K_pad] fp16 hi/lo
// ---------------------------------------------------------------------------
__device__ __forceinline__ void prep_one(const float* W, __half* dh, __half* dl,
                                         int K, int N, int K_pad, int idx) {
    int n = idx / K_pad, k = idx - n * K_pad;
    float v = (n < N && k < K) ? W[(size_t)k * N + n] : 0.0f;
    __half h, l;
    split1(v, h, l);
    dh[idx] = h;
    dl[idx] = l;
}

__global__ void prep_all(const float* W0, const float* W1, const float* W2,
                         const float* W3,
                         __half* w0h, __half* w0l, __half* w1h, __half* w1l,
                         __half* w2h, __half* w2l, __half* w3h, __half* w3l) {
    constexpr int B0 = HID * IN_PAD / 256;       // 6016
    constexpr int B1 = B0 + HID * HID / 256;     // 7040
    constexpr int B2 = B1 + HID * HID / 256;     // 8064
    int b = blockIdx.x;
    int t = threadIdx.x;
    if (b < B0) {
        prep_one(W0, w0h, w0l, IN_DIM, HID, IN_PAD, b * 256 + t);
    } else if (b < B1) {
        prep_one(W1, w1h, w1l, HID, HID, HID, (b - B0) * 256 + t);
    } else if (b < B2) {
        prep_one(W2, w2h, w2l, HID, HID, HID, (b - B1) * 256 + t);
    } else {
        prep_one(W3, w3h, w3l, HID, LAT, HID, (b - B2) * 256 + t);
    }
}

// ---------------------------------------------------------------------------
// Split-fp16 GEMM + bias + ReLU via mma.sync m16n8k16
//   NPASS==2: D = Ah*B + Al*B          (A exact split, B single fp16)
//   NPASS==3: D = Ah*Bh + Al*Bh + Ah*Bl
// Grid = (ntiles, mtiles): N-tiles of the same M-tile are linearly adjacent
// so they co-schedule and share A/X through L2.
// ---------------------------------------------------------------------------
template <int BN, int BK, int WARPS_M, int WARPS_N, int NPASS,
          bool A_FP32, bool OUT_FP32>
__global__ void __launch_bounds__(WARPS_M * WARPS_N * 32, 1)
mlp_gemm(const float* __restrict__ Xfp,
         const __half* __restrict__ Ah,
         const __half* __restrict__ Al, int lda,
         const __half* __restrict__ Bh,
         const __half* __restrict__ Bl, int ldb,
         const float* __restrict__ bias, int n_bias,
         __half* __restrict__ Oh,
         __half* __restrict__ Ol,
         float* __restrict__ Ofp, int ldo,
         int ktiles) {
    constexpr int THREADS = WARPS_M * WARPS_N * 32;
    constexpr int WM = MT / WARPS_M;
    constexpr int WN = BN / WARPS_N;
    constexpr int MF = WM / 16;
    constexpr int NF = WN / 8;
    constexpr int CPR = BK / 8;            // 16B chunks per row
    constexpr int ROWB = 2 * BK;           // row bytes
    constexpr int SWS = (BK == 64) ? 0 : 1;
    constexpr int NBBUF = (NPASS == 3) ? 2 : 1;
    constexpr int A_B = MT * ROWB;
    constexpr int B_B = BN * ROWB;
    constexpr int STAGE = 2 * A_B + NBBUF * B_B;
    constexpr int NSTAGE = 3;
    constexpr int KS_PER = BK / 16;

    extern __shared__ __align__(128) char smem[];
    float* sbias = reinterpret_cast<float*>(smem + NSTAGE * STAGE);
    const uint32_t sbase = smem_u32(smem);

    const int tid = threadIdx.x;
    const int wid = tid >> 5;
    const int lane = tid & 31;
    const int warp_m = wid % WARPS_M;
    const int warp_n = wid / WARPS_M;
    const int n0 = blockIdx.x * BN;    // N-tile fast -> pair shares A via L2
    const int m0 = blockIdx.y * MT;

    for (int i = tid; i < BN; i += THREADS)
        sbias[i] = (n0 + i < n_bias) ? bias[n0 + i] : 0.0f;

    auto toff = [](int r, int c) -> uint32_t {
        return (uint32_t)(r * ROWB + (((c ^ ((r >> SWS) & (CPR - 1)))) << 4));
    };

    // ldmatrix lane geometry (validated rounds 3-5)
    const int row_a = warp_m * WM + ((lane & 7) | (((lane >> 3) & 1) << 3));
    const int csel_a = lane >> 4;
    const int swz_a = (row_a >> SWS) & (CPR - 1);
    const int row_b = warp_n * WN + ((lane & 7) | (((lane >> 4) & 1) << 3));
    const int csel_b = (lane >> 3) & 1;
    const int swz_b = (row_b >> SWS) & (CPR - 1);

    float acc[MF][NF][4] = {};

    // pending fp32 X loads (layer-0 path): groups of 8 floats
    constexpr int NPX = A_FP32 ? (MT * CPR / THREADS) : 1;
    float4 px[NPX][2];
    uint32_t pdst[NPX];

    // ---------------- tile loaders ----------------
    auto load_B = [&](int kt, int s) {
        const uint32_t base = sbase + s * STAGE + 2 * A_B;
        #pragma unroll
        for (int it = 0; it < (NBBUF * BN * CPR) / THREADS; it++) {
            int g = it * THREADS + tid;
            int buf = g / (BN * CPR);
            int w = g - buf * (BN * CPR);
            int r = w / CPR, c = w - r * CPR;
            const __half* src =
                (buf ? Bl : Bh) + (size_t)(n0 + r) * ldb + kt * BK + c * 8;
            cp16(base + buf * B_B + toff(r, c), src);
        }
    };
    auto load_A_f16 = [&](int kt, int s) {
        const uint32_t base = sbase + s * STAGE;
        #pragma unroll
        for (int it = 0; it < (2 * MT * CPR) / THREADS; it++) {
            int g = it * THREADS + tid;
            int buf = g / (MT * CPR);
            int w = g - buf * (MT * CPR);
            int r = w / CPR, c = w - r * CPR;
            const __half* src =
                (buf ? Al : Ah) + (size_t)(m0 + r) * lda + kt * BK + c * 8;
            cp16(base + buf * A_B + toff(r, c), src);
        }
    };
    auto ldg_A_fp32 = [&](int kt) {
        #pragma unroll
        for (int it = 0; it < NPX; it++) {
            int g = it * THREADS + tid;
            int r = g / CPR, c = g - r * CPR;
            int k0 = kt * BK + c * 8;
            float4 z = make_float4(0.f, 0.f, 0.f, 0.f);
            if ((m0 + r < M_REAL) && (k0 < IN_DIM)) {
                const float4* p =
                    reinterpret_cast<const float4*>(Xfp + (size_t)(m0 + r) * lda + k0);
                px[it][0] = p[0];
                px[it][1] = p[1];
            } else {
                px[it][0] = z;
                px[it][1] = z;
            }
            pdst[it] = toff(r, c);
        }
    };
    auto sts_A_fp32 = [&](int s) {
        char* base = smem + s * STAGE;
        #pragma unroll
        for (int it = 0; it < NPX; it++) {
            float f[8] = {px[it][0].x, px[it][0].y, px[it][0].z, px[it][0].w,
                          px[it][1].x, px[it][1].y, px[it][1].z, px[it][1].w};
            uint32_t hw[4], lw[4];
            #pragma unroll
            for (int i = 0; i < 4; i++) {
                __half h0, l0, h1, l1;
                split1(f[2 * i], h0, l0);
                split1(f[2 * i + 1], h1, l1);
                hw[i] = pack_h2(h0, h1);
                lw[i] = pack_h2(l0, l1);
            }
            *reinterpret_cast<uint4*>(base + pdst[it]) =
                make_uint4(hw[0], hw[1], hw[2], hw[3]);
            *reinterpret_cast<uint4*>(base + A_B + pdst[it]) =
                make_uint4(lw[0], lw[1], lw[2], lw[3]);
        }
    };

    // ---------------- prologue: stages 0,1 ----------------
    load_B(0, 0);
    if constexpr (A_FP32) { ldg_A_fp32(0); sts_A_fp32(0); }
    else                  { load_A_f16(0, 0); }
    asm volatile("cp.async.commit_group;" ::: "memory");
    load_B(1, 1);
    if constexpr (A_FP32) { ldg_A_fp32(1); sts_A_fp32(1); }
    else                  { load_A_f16(1, 1); }
    asm volatile("cp.async.commit_group;" ::: "memory");

    // ---------------- main loop ----------------
    for (int kt = 0; kt < ktiles; kt++) {
        const int s = kt % NSTAGE;
        asm volatile("cp.async.wait_group 1;" ::: "memory");
        __syncthreads();

        const int nk = kt + 2;
        const bool pre = nk < ktiles;
        const int sn = nk % NSTAGE;
        if (pre) {
            load_B(nk, sn);
            if constexpr (A_FP32) ldg_A_fp32(nk);
            else                  load_A_f16(nk, sn);
        }

        // ---- compute stage s ----
        const uint32_t sa = sbase + s * STAGE;
        const uint32_t sb = sa + 2 * A_B;
        #pragma unroll
        for (int ks = 0; ks < KS_PER; ks++) {
            const uint32_t aoff = (uint32_t)row_a * ROWB +
                                  (uint32_t)(((ks * 2 + csel_a) ^ swz_a) << 4);
            const uint32_t boff = (uint32_t)row_b * ROWB +
                                  (uint32_t)(((ks * 2 + csel_b) ^ swz_b) << 4);
            uint32_t ah[MF][4], al[MF][4], bb[NF][2];
            // hoist ALL fragment loads ahead of the MMA block so ldsm latency
            // hides under the 32-deep independent HMMA stream
            #pragma unroll
            for (int mf = 0; mf < MF; mf++)
                ldsm4(sa + aoff + mf * 16 * ROWB,
                      ah[mf][0], ah[mf][1], ah[mf][2], ah[mf][3]);
            #pragma unroll
            for (int mf = 0; mf < MF; mf++)
                ldsm4(sa + A_B + aoff + mf * 16 * ROWB,
                      al[mf][0], al[mf][1], al[mf][2], al[mf][3]);
            #pragma unroll
            for (int nf2 = 0; nf2 < NF / 2; nf2++) {
                uint32_t r0, r1, r2, r3;
                ldsm4(sb + boff + nf2 * 16 * ROWB, r0, r1, r2, r3);
                bb[2 * nf2][0] = r0; bb[2 * nf2][1] = r1;
                bb[2 * nf2 + 1][0] = r2; bb[2 * nf2 + 1][1] = r3;
            }
            // pass 1: Ah * B(h)
            #pragma unroll
            for (int mf = 0; mf < MF; mf++)
                #pragma unroll
                for (int nf = 0; nf < NF; nf++)
                    mma16816(acc[mf][nf], ah[mf], bb[nf]);
            // pass 2: Al * B(h)
            #pragma unroll
            for (int mf = 0; mf < MF; mf++)
                #pragma unroll
                for (int nf = 0; nf < NF; nf++)
                    mma16816(acc[mf][nf], al[mf], bb[nf]);
            // pass 3: Ah * Bl
            if constexpr (NPASS == 3) {
                #pragma unroll
                for (int nf2 = 0; nf2 < NF / 2; nf2++) {
                    uint32_t r0, r1, r2, r3;
                    ldsm4(sb + B_B + boff + nf2 * 16 * ROWB, r0, r1, r2, r3);
                    bb[2 * nf2][0] = r0; bb[2 * nf2][1] = r1;
                    bb[2 * nf2 + 1][0] = r2; bb[2 * nf2 + 1][1] = r3;
                }
                #pragma unroll
                for (int mf = 0; mf < MF; mf++)
                    #pragma unroll
                    for (int nf = 0; nf < NF; nf++)
                        mma16816(acc[mf][nf], ah[mf], bb[nf]);
            }
        }

        if (pre) { if constexpr (A_FP32) sts_A_fp32(sn); }
        asm volatile("cp.async.commit_group;" ::: "memory");
    }

    // ---------------- epilogue: bias + ReLU + store ----------------
    const int gid = lane >> 2;
    const int tig = lane & 3;
    #pragma unroll
    for (int mf = 0; mf < MF; mf++) {
        #pragma unroll
        for (int nf = 0; nf < NF; nf++) {
            const int col0 = warp_n * WN + nf * 8 + tig * 2;
            const float bv0 = sbias[col0], bv1 = sbias[col0 + 1];
            #pragma unroll
            for (int half = 0; half < 2; half++) {
                const int m = m0 + warp_m * WM + mf * 16 + gid + half * 8;
                float v0 = fmaxf(acc[mf][nf][2 * half + 0] + bv0, 0.0f);
                float v1 = fmaxf(acc[mf][nf][2 * half + 1] + bv1, 0.0f);
                if (m < M_REAL) {
                    if constexpr (OUT_FP32) {
                        if (col0 < LAT)     Ofp[(size_t)m * ldo + col0]     = v0;
                        if (col0 + 1 < LAT) Ofp[(size_t)m * ldo + col0 + 1] = v1;
                    } else {
                        __half h0, l0, h1, l1;
                        split1(v0, h0, l0);
                        split1(v1, h1, l1);
                        const size_t idx = (size_t)m * ldo + n0 + col0;
                        *reinterpret_cast<uint32_t*>(Oh + idx) = pack_h2(h0, h1);
                        *reinterpret_cast<uint32_t*>(Ol + idx) = pack_h2(l0, l1);
                    }
                }
            }
        }
    }
}

// ---------------------------------------------------------------------------
// Host launch
// ---------------------------------------------------------------------------
extern "C" void kernel_launch(void* const* d_in, const int* in_sizes, int n_in,
                              void* d_out, int out_size) {
    const float* X  = (const float*)d_in[0];
    // d_in[1] = g (dead)
    const float* W0 = (const float*)d_in[2];
    const float* b0 = (const float*)d_in[3];
    const float* W1 = (const float*)d_in[4];
    const float* b1 = (const float*)d_in[5];
    const float* W2 = (const float*)d_in[6];
    const float* b2 = (const float*)d_in[7];
    const float* W3 = (const float*)d_in[8];
    const float* b3 = (const float*)d_in[9];
    float* out = (float*)d_out;

    void *w0h, *w0l, *w1h, *w1l, *w2h, *w2l, *w3h, *w3l, *hah, *hal, *hbh, *hbl;
    cudaGetSymbolAddress(&w0h, g_W0h); cudaGetSymbolAddress(&w0l, g_W0l);
    cudaGetSymbolAddress(&w1h, g_W1h); cudaGetSymbolAddress(&w1l, g_W1l);
    cudaGetSymbolAddress(&w2h, g_W2h); cudaGetSymbolAddress(&w2l, g_W2l);
    cudaGetSymbolAddress(&w3h, g_W3h); cudaGetSymbolAddress(&w3l, g_W3l);
    cudaGetSymbolAddress(&hah, g_Hah); cudaGetSymbolAddress(&hal, g_Hal);
    cudaGetSymbolAddress(&hbh, g_Hbh); cudaGetSymbolAddress(&hbl, g_Hbl);

    // single fused weight-prep launch
    constexpr int PREP_BLOCKS =
        HID * IN_PAD / 256 + HID * HID / 256 + HID * HID / 256 + 32 * HID / 256;
    prep_all<<<PREP_BLOCKS, 256>>>(
        W0, W1, W2, W3,
        (__half*)w0h, (__half*)w0l, (__half*)w1h, (__half*)w1l,
        (__half*)w2h, (__half*)w2l, (__half*)w3h, (__half*)w3l);

    const int mtiles = (M_REAL + MT - 1) / MT;  // 782

    // smem sizes (3 stages + bias)
    constexpr int SM_2P = 3 * (2 * MT * 128 + 1 * 256 * 128) + 256 * 4;  // 197632
    constexpr int SM_L3 = 3 * (2 * MT * 64 + 2 * 32 * 64) + 32 * 4;      // 61568

    cudaFuncSetAttribute((const void*)mlp_gemm<256, 64, 2, 4, 2, true, false>,
                         cudaFuncAttributeMaxDynamicSharedMemorySize, SM_2P);
    cudaFuncSetAttribute((const void*)mlp_gemm<256, 64, 2, 4, 2, false, false>,
                         cudaFuncAttributeMaxDynamicSharedMemorySize, SM_2P);
    cudaFuncSetAttribute((const void*)mlp_gemm<32, 32, 4, 2, 3, false, true>,
                         cudaFuncAttributeMaxDynamicSharedMemorySize, SM_L3);

    // layer 0: X fp32 (split inline, exact) x W0 (single fp16), 2-pass, BK=64
    mlp_gemm<256, 64, 2, 4, 2, true, false><<<dim3(2, mtiles), 256, SM_2P>>>(
        X, nullptr, nullptr, IN_DIM,
        (const __half*)w0h, (const __half*)w0l, IN_PAD,
        b0, HID,
        (__half*)hah, (__half*)hal, nullptr, HID, IN_PAD / 64);

    // layer 1: Ha (split, exact) x W1 (single fp16), 2-pass, BK=64
    mlp_gemm<256, 64, 2, 4, 2, false, false><<<dim3(2, mtiles), 256, SM_2P>>>(
        nullptr, (const __half*)hah, (const __half*)hal, HID,
        (const __half*)w1h, (const __half*)w1l, HID,
        b1, HID,
        (__half*)hbh, (__half*)hbl, nullptr, HID, HID / 64);

    // layer 2: Hb -> Ha, 2-pass, BK=64
    mlp_gemm<256, 64, 2, 4, 2, false, false><<<dim3(2, mtiles), 256, SM_2P>>>(
        nullptr, (const __half*)hbh, (const __half*)hbl, HID,
        (const __half*)w2h, (const __half*)w2l, HID,
        b2, HID,
        (__half*)hah, (__half*)hal, nullptr, HID, HID / 64);

    // layer 3: Ha -> out fp32 [100000, 20], 3-pass (cheap accuracy hedge)
    mlp_gemm<32, 32, 4, 2, 3, false, true><<<dim3(1, mtiles), 256, SM_L3>>>(
        nullptr, (const __half*)hah, (const __half*)hal, HID,
        (const __half*)w3h, (const __half*)w3l, HID,
        b3, LAT,
        nullptr, nullptr, out, LAT, HID / 32);

    (void)in_sizes; (void)n_in; (void)out_size;
}

// round 9
// speedup vs baseline: 1.7226x; 1.1298x over previous
#include <cuda_runtime.h>
#include <cuda_fp16.h>
#include <cstdint>
#include <cstddef>

// ---------------------------------------------------------------------------
// Problem constants
// ---------------------------------------------------------------------------
static constexpr int IN_DIM  = 3000;
static constexpr int IN_PAD  = 3008;    // K padded to multiple of 64
static constexpr int HID     = 512;
static constexpr int LAT     = 20;
static constexpr int M_REAL  = 100000;
static constexpr int M_PAD   = 100096;  // 782 * 128
static constexpr int MT      = 128;     // CTA M tile

// ---------------------------------------------------------------------------
// Static device scratch (allocation-free rule)
// Weights transposed to [N][K_pad] fp16, zero padded. W3 kept hi/lo split
// (2-pass on the tiny last layer is a near-free accuracy hedge).
// Activations stored as single fp16 (1-pass scheme), rows padded to M_PAD.
// ---------------------------------------------------------------------------
__device__ __align__(16) __half g_W0h[HID * IN_PAD];
__device__ __align__(16) __half g_W1h[HID * HID];
__device__ __align__(16) __half g_W2h[HID * HID];
__device__ __align__(16) __half g_W3h[32 * HID];
__device__ __align__(16) __half g_W3l[32 * HID];
__device__ __align__(16) __half g_Ha[(size_t)M_PAD * HID];
__device__ __align__(16) __half g_Hb[(size_t)M_PAD * HID];

// ---------------------------------------------------------------------------
// Helpers
// ---------------------------------------------------------------------------
__device__ __forceinline__ uint32_t smem_u32(const void* p) {
    uint32_t a;
    asm("{ .reg .u64 t; cvta.to.shared.u64 t, %1; cvt.u32.u64 %0, t; }"
        : "=r"(a) : "l"(p));
    return a;
}

__device__ __forceinline__ void cp16(uint32_t dst, const void* src) {
    asm volatile("cp.async.cg.shared.global [%0], [%1], 16;"
                 :: "r"(dst), "l"(src) : "memory");
}

__device__ __forceinline__ void ldsm4(uint32_t addr, uint32_t& r0, uint32_t& r1,
                                      uint32_t& r2, uint32_t& r3) {
    asm volatile("ldmatrix.sync.aligned.m8n8.x4.shared.b16 {%0,%1,%2,%3}, [%4];"
                 : "=r"(r0), "=r"(r1), "=r"(r2), "=r"(r3) : "r"(addr));
}

__device__ __forceinline__ void mma16816(float* c, const uint32_t* a, const uint32_t* b) {
    asm volatile(
        "mma.sync.aligned.m16n8k16.row.col.f32.f16.f16.f32 "
        "{%0,%1,%2,%3}, {%4,%5,%6,%7}, {%8,%9}, {%0,%1,%2,%3};"
        : "+f"(c[0]), "+f"(c[1]), "+f"(c[2]), "+f"(c[3])
        : "r"(a[0]), "r"(a[1]), "r"(a[2]), "r"(a[3]), "r"(b[0]), "r"(b[1]));
}

__device__ __forceinline__ void split1(float v, __half& h, __half& l) {
    h = __float2half(v);
    l = __float2half(v - __half2float(h));
}

__device__ __forceinline__ uint32_t pack_h2(__half a, __half b) {
    __half2 t = __halves2half2(a, b);  // .x = a (low half)
    return *reinterpret_cast<uint32_t*>(&t);
}

// ---------------------------------------------------------------------------
// Fused weight prep (one launch):
//   W0/W1/W2: W[K][N] fp32 -> Wt[N_pad][K_pad] fp16 (round-to-nearest)
//   W3:       split hi/lo
// ---------------------------------------------------------------------------
__device__ __forceinline__ void prep_h(const float* W, __half* dh,
                                       int K, int N, int K_pad, int idx) {
    int n = idx / K_pad, k = idx - n * K_pad;
    float v = (n < N && k < K) ? W[(size_t)k * N + n] : 0.0f;
    dh[idx] = __float2half(v);
}

__global__ void prep_all(const float* W0, const float* W1, const float* W2,
                         const float* W3,
                         __half* w0h, __half* w1h, __half* w2h,
                         __half* w3h, __half* w3l) {
    constexpr int B0 = HID * IN_PAD / 256;       // 6016
    constexpr int B1 = B0 + HID * HID / 256;     // 7040
    constexpr int B2 = B1 + HID * HID / 256;     // 8064
    int b = blockIdx.x;
    int t = threadIdx.x;
    if (b < B0) {
        prep_h(W0, w0h, IN_DIM, HID, IN_PAD, b * 256 + t);
    } else if (b < B1) {
        prep_h(W1, w1h, HID, HID, HID, (b - B0) * 256 + t);
    } else if (b < B2) {
        prep_h(W2, w2h, HID, HID, HID, (b - B1) * 256 + t);
    } else {
        int idx = (b - B2) * 256 + t;
        int n = idx / HID, k = idx - n * HID;
        float v = (n < LAT) ? W3[(size_t)k * LAT + n] : 0.0f;
        __half h, l;
        split1(v, h, l);
        w3h[idx] = h;
        w3l[idx] = l;
    }
}

// ---------------------------------------------------------------------------
// fp16 GEMM + bias + ReLU via mma.sync m16n8k16
//   BSPLIT=false: D = A*B            (1 pass)
//   BSPLIT=true : D = A*Bh + A*Bl    (2 passes, exact-split B)
// Grid = (ntiles, mtiles): N-tiles of one M-tile adjacent -> share A via L2.
// 3-stage cp.async pipeline; fragment double-buffering across k-steps.
// ---------------------------------------------------------------------------
template <int BN, int BK, int WARPS_M, int WARPS_N, bool BSPLIT,
          bool A_FP32, bool OUT_FP32>
__global__ void __launch_bounds__(WARPS_M * WARPS_N * 32, 1)
mlp_gemm(const float* __restrict__ Xfp,
         const __half* __restrict__ A, int lda,
         const __half* __restrict__ Bh,
         const __half* __restrict__ Bl, int ldb,
         const float* __restrict__ bias, int n_bias,
         __half* __restrict__ Oh,
         float* __restrict__ Ofp, int ldo,
         int ktiles) {
    constexpr int THREADS = WARPS_M * WARPS_N * 32;
    constexpr int WM = MT / WARPS_M;
    constexpr int WN = BN / WARPS_N;
    constexpr int MF = WM / 16;
    constexpr int NF = WN / 8;
    constexpr int CPR = BK / 8;            // 16B chunks per row
    constexpr int ROWB = 2 * BK;           // row bytes
    constexpr int SWS = (BK == 64) ? 0 : 1;
    constexpr int NBBUF = BSPLIT ? 2 : 1;
    constexpr int A_B = MT * ROWB;
    constexpr int B_B = BN * ROWB;
    constexpr int STAGE = A_B + NBBUF * B_B;
    constexpr int NSTAGE = 3;
    constexpr int KS_PER = BK / 16;

    extern __shared__ __align__(128) char smem[];
    float* sbias = reinterpret_cast<float*>(smem + NSTAGE * STAGE);
    const uint32_t sbase = smem_u32(smem);

    const int tid = threadIdx.x;
    const int wid = tid >> 5;
    const int lane = tid & 31;
    const int warp_m = wid % WARPS_M;
    const int warp_n = wid / WARPS_M;
    const int n0 = blockIdx.x * BN;    // N-tile fast -> pair shares A via L2
    const int m0 = blockIdx.y * MT;

    for (int i = tid; i < BN; i += THREADS)
        sbias[i] = (n0 + i < n_bias) ? bias[n0 + i] : 0.0f;

    auto toff = [](int r, int c) -> uint32_t {
        return (uint32_t)(r * ROWB + (((c ^ ((r >> SWS) & (CPR - 1)))) << 4));
    };

    // ldmatrix lane geometry (validated rounds 3-7)
    const int row_a = warp_m * WM + ((lane & 7) | (((lane >> 3) & 1) << 3));
    const int csel_a = lane >> 4;
    const int swz_a = (row_a >> SWS) & (CPR - 1);
    const int row_b = warp_n * WN + ((lane & 7) | (((lane >> 4) & 1) << 3));
    const int csel_b = (lane >> 3) & 1;
    const int swz_b = (row_b >> SWS) & (CPR - 1);

    float acc[MF][NF][4] = {};

    // pending fp32 X loads (layer-0 path): groups of 8 floats
    constexpr int NPX = A_FP32 ? (MT * CPR / THREADS) : 1;
    float4 px[NPX][2];
    uint32_t pdst[NPX];

    // ---------------- tile loaders ----------------
    auto load_B = [&](int kt, int s) {
        const uint32_t base = sbase + s * STAGE + A_B;
        #pragma unroll
        for (int it = 0; it < (NBBUF * BN * CPR) / THREADS; it++) {
            int g = it * THREADS + tid;
            int buf = g / (BN * CPR);
            int w = g - buf * (BN * CPR);
            int r = w / CPR, c = w - r * CPR;
            const __half* src =
                (buf ? Bl : Bh) + (size_t)(n0 + r) * ldb + kt * BK + c * 8;
            cp16(base + buf * B_B + toff(r, c), src);
        }
    };
    auto load_A_f16 = [&](int kt, int s) {
        const uint32_t base = sbase + s * STAGE;
        #pragma unroll
        for (int it = 0; it < (MT * CPR) / THREADS; it++) {
            int g = it * THREADS + tid;
            int r = g / CPR, c = g - r * CPR;
            const __half* src = A + (size_t)(m0 + r) * lda + kt * BK + c * 8;
            cp16(base + toff(r, c), src);
        }
    };
    auto ldg_A_fp32 = [&](int kt) {
        #pragma unroll
        for (int it = 0; it < NPX; it++) {
            int g = it * THREADS + tid;
            int r = g / CPR, c = g - r * CPR;
            int k0 = kt * BK + c * 8;
            float4 z = make_float4(0.f, 0.f, 0.f, 0.f);
            if ((m0 + r < M_REAL) && (k0 < IN_DIM)) {
                const float4* p =
                    reinterpret_cast<const float4*>(Xfp + (size_t)(m0 + r) * lda + k0);
                px[it][0] = p[0];
                px[it][1] = p[1];
            } else {
                px[it][0] = z;
                px[it][1] = z;
            }
            pdst[it] = toff(r, c);
        }
    };
    auto sts_A_fp32 = [&](int s) {
        char* base = smem + s * STAGE;
        #pragma unroll
        for (int it = 0; it < NPX; it++) {
            float f[8] = {px[it][0].x, px[it][0].y, px[it][0].z, px[it][0].w,
                          px[it][1].x, px[it][1].y, px[it][1].z, px[it][1].w};
            uint32_t hw[4];
            #pragma unroll
            for (int i = 0; i < 4; i++)
                hw[i] = pack_h2(__float2half(f[2 * i]), __float2half(f[2 * i + 1]));
            *reinterpret_cast<uint4*>(base + pdst[it]) =
                make_uint4(hw[0], hw[1], hw[2], hw[3]);
        }
    };

    // ---------------- prologue: stages 0,1 ----------------
    load_B(0, 0);
    if constexpr (A_FP32) { ldg_A_fp32(0); sts_A_fp32(0); }
    else                  { load_A_f16(0, 0); }
    asm volatile("cp.async.commit_group;" ::: "memory");
    load_B(1, 1);
    if constexpr (A_FP32) { ldg_A_fp32(1); sts_A_fp32(1); }
    else                  { load_A_f16(1, 1); }
    asm volatile("cp.async.commit_group;" ::: "memory");

    // ---------------- main loop ----------------
    for (int kt = 0; kt < ktiles; kt++) {
        const int s = kt % NSTAGE;
        asm volatile("cp.async.wait_group 1;" ::: "memory");
        __syncthreads();

        const uint32_t sa = sbase + s * STAGE;
        const uint32_t sb = sa + A_B;

        const int nk = kt + 2;
        const bool pre = nk < ktiles;
        const int sn = nk % NSTAGE;

        if constexpr (!BSPLIT) {
            // frag double-buffer across the KS_PER k-steps
            uint32_t ah[2][MF][4], bb[2][NF][2];
            auto ldfrag = [&](int ks, int d) {
                const uint32_t aoff = (uint32_t)row_a * ROWB +
                                      (uint32_t)((((ks << 1) + csel_a) ^ swz_a) << 4);
                const uint32_t boff = (uint32_t)row_b * ROWB +
                                      (uint32_t)((((ks << 1) + csel_b) ^ swz_b) << 4);
                #pragma unroll
                for (int mf = 0; mf < MF; mf++)
                    ldsm4(sa + aoff + mf * 16 * ROWB,
                          ah[d][mf][0], ah[d][mf][1], ah[d][mf][2], ah[d][mf][3]);
                #pragma unroll
                for (int nf2 = 0; nf2 < NF / 2; nf2++) {
                    uint32_t r0, r1, r2, r3;
                    ldsm4(sb + boff + nf2 * 16 * ROWB, r0, r1, r2, r3);
                    bb[d][2 * nf2][0] = r0; bb[d][2 * nf2][1] = r1;
                    bb[d][2 * nf2 + 1][0] = r2; bb[d][2 * nf2 + 1][1] = r3;
                }
            };
            ldfrag(0, 0);                       // start frags ASAP
            if (pre) {                          // then queue next tile's loads
                load_B(nk, sn);
                if constexpr (A_FP32) ldg_A_fp32(nk);
                else                  load_A_f16(nk, sn);
            }
            #pragma unroll
            for (int ks = 0; ks < KS_PER; ks++) {
                const int cur = ks & 1;
                if (ks + 1 < KS_PER) ldfrag(ks + 1, cur ^ 1);
                #pragma unroll
                for (int mf = 0; mf < MF; mf++)
                    #pragma unroll
                    for (int nf = 0; nf < NF; nf++)
                        mma16816(acc[mf][nf], ah[cur][mf], bb[cur][nf]);
            }
        } else {
            // small-layer path (L3): simple 2-pass with exact-split B
            if (pre) {
                load_B(nk, sn);
                load_A_f16(nk, sn);
            }
            #pragma unroll
            for (int ks = 0; ks < KS_PER; ks++) {
                const uint32_t aoff = (uint32_t)row_a * ROWB +
                                      (uint32_t)((((ks << 1) + csel_a) ^ swz_a) << 4);
                const uint32_t boff = (uint32_t)row_b * ROWB +
                                      (uint32_t)((((ks << 1) + csel_b) ^ swz_b) << 4);
                uint32_t ah[MF][4], bb[NF][2];
                #pragma unroll
                for (int mf = 0; mf < MF; mf++)
                    ldsm4(sa + aoff + mf * 16 * ROWB,
                          ah[mf][0], ah[mf][1], ah[mf][2], ah[mf][3]);
                #pragma unroll
                for (int nf2 = 0; nf2 < NF / 2; nf2++) {
                    uint32_t r0, r1, r2, r3;
                    ldsm4(sb + boff + nf2 * 16 * ROWB, r0, r1, r2, r3);
                    bb[2 * nf2][0] = r0; bb[2 * nf2][1] = r1;
                    bb[2 * nf2 + 1][0] = r2; bb[2 * nf2 + 1][1] = r3;
                }
                #pragma unroll
                for (int mf = 0; mf < MF; mf++)
                    #pragma unroll
                    for (int nf = 0; nf < NF; nf++)
                        mma16816(acc[mf][nf], ah[mf], bb[nf]);
                #pragma unroll
                for (int nf2 = 0; nf2 < NF / 2; nf2++) {
                    uint32_t r0, r1, r2, r3;
                    ldsm4(sb + B_B + boff + nf2 * 16 * ROWB, r0, r1, r2, r3);
                    bb[2 * nf2][0] = r0; bb[2 * nf2][1] = r1;
                    bb[2 * nf2 + 1][0] = r2; bb[2 * nf2 + 1][1] = r3;
                }
                #pragma unroll
                for (int mf = 0; mf < MF; mf++)
                    #pragma unroll
                    for (int nf = 0; nf < NF; nf++)
                        mma16816(acc[mf][nf], ah[mf], bb[nf]);
            }
        }

        if (pre) { if constexpr (A_FP32) sts_A_fp32(sn); }
        asm volatile("cp.async.commit_group;" ::: "memory");
    }

    // ---------------- epilogue: bias + ReLU + store ----------------
    const int gid = lane >> 2;
    const int tig = lane & 3;
    #pragma unroll
    for (int mf = 0; mf < MF; mf++) {
        #pragma unroll
        for (int nf = 0; nf < NF; nf++) {
            const int col0 = warp_n * WN + nf * 8 + tig * 2;
            const float bv0 = sbias[col0], bv1 = sbias[col0 + 1];
            #pragma unroll
            for (int half = 0; half < 2; half++) {
                const int m = m0 + warp_m * WM + mf * 16 + gid + half * 8;
                float v0 = fmaxf(acc[mf][nf][2 * half + 0] + bv0, 0.0f);
                float v1 = fmaxf(acc[mf][nf][2 * half + 1] + bv1, 0.0f);
                if (m < M_REAL) {
                    if constexpr (OUT_FP32) {
                        if (col0 < LAT)     Ofp[(size_t)m * ldo + col0]     = v0;
                        if (col0 + 1 < LAT) Ofp[(size_t)m * ldo + col0 + 1] = v1;
                    } else {
                        const size_t idx = (size_t)m * ldo + n0 + col0;
                        *reinterpret_cast<uint32_t*>(Oh + idx) =
                            pack_h2(__float2half(v0), __float2half(v1));
                    }
                }
            }
        }
    }
}

// ---------------------------------------------------------------------------
// Host launch
// ---------------------------------------------------------------------------
extern "C" void kernel_launch(void* const* d_in, const int* in_sizes, int n_in,
                              void* d_out, int out_size) {
    const float* X  = (const float*)d_in[0];
    // d_in[1] = g (dead)
    const float* W0 = (const float*)d_in[2];
    const float* b0 = (const float*)d_in[3];
    const float* W1 = (const float*)d_in[4];
    const float* b1 = (const float*)d_in[5];
    const float* W2 = (const float*)d_in[6];
    const float* b2 = (const float*)d_in[7];
    const float* W3 = (const float*)d_in[8];
    const float* b3 = (const float*)d_in[9];
    float* out = (float*)d_out;

    void *w0h, *w1h, *w2h, *w3h, *w3l, *ha, *hb;
    cudaGetSymbolAddress(&w0h, g_W0h);
    cudaGetSymbolAddress(&w1h, g_W1h);
    cudaGetSymbolAddress(&w2h, g_W2h);
    cudaGetSymbolAddress(&w3h, g_W3h); cudaGetSymbolAddress(&w3l, g_W3l);
    cudaGetSymbolAddress(&ha, g_Ha);   cudaGetSymbolAddress(&hb, g_Hb);

    // single fused weight-prep launch
    constexpr int PREP_BLOCKS =
        HID * IN_PAD / 256 + HID * HID / 256 + HID * HID / 256 + 32 * HID / 256;
    prep_all<<<PREP_BLOCKS, 256>>>(
        W0, W1, W2, W3,
        (__half*)w0h, (__half*)w1h, (__half*)w2h, (__half*)w3h, (__half*)w3l);

    const int mtiles = (M_REAL + MT - 1) / MT;  // 782

    // smem sizes (3 stages + bias)
    constexpr int SM_1P = 3 * (MT * 128 + 256 * 128) + 256 * 4;      // 148480
    constexpr int SM_L3 = 3 * (MT * 128 + 2 * 32 * 128) + 32 * 4;    // 73856

    cudaFuncSetAttribute((const void*)mlp_gemm<256, 64, 2, 4, false, true, false>,
                         cudaFuncAttributeMaxDynamicSharedMemorySize, SM_1P);
    cudaFuncSetAttribute((const void*)mlp_gemm<256, 64, 2, 4, false, false, false>,
                         cudaFuncAttributeMaxDynamicSharedMemorySize, SM_1P);
    cudaFuncSetAttribute((const void*)mlp_gemm<32, 64, 4, 2, true, false, true>,
                         cudaFuncAttributeMaxDynamicSharedMemorySize, SM_L3);

    // layer 0: X fp32 (inline fp16 convert) x W0 fp16, 1-pass, BK=64
    mlp_gemm<256, 64, 2, 4, false, true, false><<<dim3(2, mtiles), 256, SM_1P>>>(
        X, nullptr, IN_DIM,
        (const __half*)w0h, nullptr, IN_PAD,
        b0, HID,
        (__half*)ha, nullptr, HID, IN_PAD / 64);

    // layer 1: Ha x W1, 1-pass
    mlp_gemm<256, 64, 2, 4, false, false, false><<<dim3(2, mtiles), 256, SM_1P>>>(
        nullptr, (const __half*)ha, HID,
        (const __half*)w1h, nullptr, HID,
        b1, HID,
        (__half*)hb, nullptr, HID, HID / 64);

    // layer 2: Hb x W2, 1-pass
    mlp_gemm<256, 64, 2, 4, false, false, false><<<dim3(2, mtiles), 256, SM_1P>>>(
        nullptr, (const __half*)hb, HID,
        (const __half*)w2h, nullptr, HID,
        b2, HID,
        (__half*)ha, nullptr, HID, HID / 64);

    // layer 3: Ha x (W3h + W3l), 2-pass exact-split B, fp32 out [100000, 20]
    mlp_gemm<32, 64, 4, 2, true, false, true><<<dim3(1, mtiles), 256, SM_L3>>>(
        nullptr, (const __half*)ha, HID,
        (const __half*)w3h, (const __half*)w3l, HID,
        b3, LAT,
        nullptr, out, LAT, HID / 64);

    (void)in_sizes; (void)n_in; (void)out_size;
}

// round 15
// speedup vs baseline: 2.0162x; 1.1705x over previous
#include <cuda_runtime.h>
#include <cuda_fp16.h>
#include <cstdint>
#include <cstddef>

// ---------------------------------------------------------------------------
// Problem constants
// ---------------------------------------------------------------------------
static constexpr int IN_DIM  = 3000;
static constexpr int IN_PAD  = 3008;    // K padded to multiple of 64
static constexpr int HID     = 512;
static constexpr int LAT     = 20;
static constexpr int M_REAL  = 100000;
static constexpr int M_PAD   = 100096;  // 782 * 128
static constexpr int MT      = 128;     // CTA M tile

// ---------------------------------------------------------------------------
// Static device scratch (allocation-free rule)
// ---------------------------------------------------------------------------
__device__ __align__(16) __half g_W0h[HID * IN_PAD];
__device__ __align__(16) __half g_W1h[HID * HID];
__device__ __align__(16) __half g_W2h[HID * HID];
__device__ __align__(16) __half g_W3h[32 * HID];
__device__ __align__(16) __half g_W3l[32 * HID];
__device__ __align__(16) __half g_Ha[(size_t)M_PAD * HID];
__device__ __align__(16) __half g_Hb[(size_t)M_PAD * HID];

// ---------------------------------------------------------------------------
// Helpers
// ---------------------------------------------------------------------------
__device__ __forceinline__ uint32_t smem_u32(const void* p) {
    uint32_t a;
    asm("{ .reg .u64 t; cvta.to.shared.u64 t, %1; cvt.u32.u64 %0, t; }"
        : "=r"(a) : "l"(p));
    return a;
}

__device__ __forceinline__ void cp16(uint32_t dst, const void* src) {
    asm volatile("cp.async.cg.shared.global [%0], [%1], 16;"
                 :: "r"(dst), "l"(src) : "memory");
}

__device__ __forceinline__ void ldsm4(uint32_t addr, uint32_t& r0, uint32_t& r1,
                                      uint32_t& r2, uint32_t& r3) {
    asm volatile("ldmatrix.sync.aligned.m8n8.x4.shared.b16 {%0,%1,%2,%3}, [%4];"
                 : "=r"(r0), "=r"(r1), "=r"(r2), "=r"(r3) : "r"(addr));
}

__device__ __forceinline__ void mma16816(float* c, const uint32_t* a, const uint32_t* b) {
    asm volatile(
        "mma.sync.aligned.m16n8k16.row.col.f32.f16.f16.f32 "
        "{%0,%1,%2,%3}, {%4,%5,%6,%7}, {%8,%9}, {%0,%1,%2,%3};"
        : "+f"(c[0]), "+f"(c[1]), "+f"(c[2]), "+f"(c[3])
        : "r"(a[0]), "r"(a[1]), "r"(a[2]), "r"(a[3]), "r"(b[0]), "r"(b[1]));
}

__device__ __forceinline__ void split1(float v, __half& h, __half& l) {
    h = __float2half(v);
    l = __float2half(v - __half2float(h));
}

__device__ __forceinline__ uint32_t pack_h2(__half a, __half b) {
    __half2 t = __halves2half2(a, b);  // .x = a (low half)
    return *reinterpret_cast<uint32_t*>(&t);
}

// ---------------------------------------------------------------------------
// Fused weight prep (one launch)
// ---------------------------------------------------------------------------
__device__ __forceinline__ void prep_h(const float* W, __half* dh,
                                       int K, int N, int K_pad, int idx) {
    int n = idx / K_pad, k = idx - n * K_pad;
    float v = (n < N && k < K) ? W[(size_t)k * N + n] : 0.0f;
    dh[idx] = __float2half(v);
}

__global__ void prep_all(const float* W0, const float* W1, const float* W2,
                         const float* W3,
                         __half* w0h, __half* w1h, __half* w2h,
                         __half* w3h, __half* w3l) {
    constexpr int B0 = HID * IN_PAD / 256;       // 6016
    constexpr int B1 = B0 + HID * HID / 256;     // 7040
    constexpr int B2 = B1 + HID * HID / 256;     // 8064
    int b = blockIdx.x;
    int t = threadIdx.x;
    if (b < B0) {
        prep_h(W0, w0h, IN_DIM, HID, IN_PAD, b * 256 + t);
    } else if (b < B1) {
        prep_h(W1, w1h, HID, HID, HID, (b - B0) * 256 + t);
    } else if (b < B2) {
        prep_h(W2, w2h, HID, HID, HID, (b - B1) * 256 + t);
    } else {
        int idx = (b - B2) * 256 + t;
        int n = idx / HID, k = idx - n * HID;
        float v = (n < LAT) ? W3[(size_t)k * LAT + n] : 0.0f;
        __half h, l;
        split1(v, h, l);
        w3h[idx] = h;
        w3l[idx] = l;
    }
}

// ---------------------------------------------------------------------------
// fp16 GEMM + bias + ReLU via mma.sync m16n8k16
//   BSPLIT=false: D = A*B            (1 pass)
//   BSPLIT=true : D = A*Bh + A*Bl    (2 passes, exact-split B)
// Grid = (ntiles, mtiles). 3-stage cp.async pipeline. MIN_CTAS=2 for the main
// layers so two CTAs co-reside and cover barrier stalls.
// PIPELINE INVARIANT: exactly one commit_group per loop iteration (empty when
// not prefetching) so wait_group 1 always drains the stage consumed next.
// ---------------------------------------------------------------------------
template <int BN, int BK, int WARPS_M, int WARPS_N, int MIN_CTAS, bool BSPLIT,
          bool A_FP32, bool OUT_FP32>
__global__ void __launch_bounds__(WARPS_M * WARPS_N * 32, MIN_CTAS)
mlp_gemm(const float* __restrict__ Xfp,
         const __half* __restrict__ A, int lda,
         const __half* __restrict__ Bh,
         const __half* __restrict__ Bl, int ldb,
         const float* __restrict__ bias, int n_bias,
         __half* __restrict__ Oh,
         float* __restrict__ Ofp, int ldo,
         int ktiles) {
    constexpr int THREADS = WARPS_M * WARPS_N * 32;
    constexpr int WM = MT / WARPS_M;
    constexpr int WN = BN / WARPS_N;
    constexpr int MF = WM / 16;
    constexpr int NF = WN / 8;
    constexpr int CPR = BK / 8;            // 16B chunks per row
    constexpr int ROWB = 2 * BK;           // row bytes
    constexpr int SWS = (BK == 64) ? 0 : 1;
    constexpr int NBBUF = BSPLIT ? 2 : 1;
    constexpr int A_B = MT * ROWB;
    constexpr int B_B = BN * ROWB;
    constexpr int STAGE = A_B + NBBUF * B_B;
    constexpr int NSTAGE = 3;
    constexpr int KS_PER = BK / 16;

    extern __shared__ __align__(128) char smem[];
    float* sbias = reinterpret_cast<float*>(smem + NSTAGE * STAGE);
    const uint32_t sbase = smem_u32(smem);

    const int tid = threadIdx.x;
    const int wid = tid >> 5;
    const int lane = tid & 31;
    const int warp_m = wid % WARPS_M;
    const int warp_n = wid / WARPS_M;
    const int n0 = blockIdx.x * BN;    // N-tile fast -> group shares A via L2
    const int m0 = blockIdx.y * MT;

    for (int i = tid; i < BN; i += THREADS)
        sbias[i] = (n0 + i < n_bias) ? bias[n0 + i] : 0.0f;

    auto toff = [](int r, int c) -> uint32_t {
        return (uint32_t)(r * ROWB + (((c ^ ((r >> SWS) & (CPR - 1)))) << 4));
    };

    // ldmatrix lane geometry (validated rounds 3-9)
    const int row_a = warp_m * WM + ((lane & 7) | (((lane >> 3) & 1) << 3));
    const int csel_a = lane >> 4;
    const int swz_a = (row_a >> SWS) & (CPR - 1);
    const int row_b = warp_n * WN + ((lane & 7) | (((lane >> 4) & 1) << 3));
    const int csel_b = (lane >> 3) & 1;
    const int swz_b = (row_b >> SWS) & (CPR - 1);

    float acc[MF][NF][4] = {};

    // ---------------- tile prefetch (one stage, one commit) ----------------
    auto prefetch = [&](int kt, int s) {
        const uint32_t bbase = sbase + s * STAGE + A_B;
        #pragma unroll
        for (int it = 0; it < (NBBUF * BN * CPR) / THREADS; it++) {
            int g = it * THREADS + tid;
            int buf = g / (BN * CPR);
            int w = g - buf * (BN * CPR);
            int r = w / CPR, c = w - r * CPR;
            const __half* src =
                (buf ? Bl : Bh) + (size_t)(n0 + r) * ldb + kt * BK + c * 8;
            cp16(bbase + buf * B_B + toff(r, c), src);
        }
        if constexpr (A_FP32) {
            // LDG fp32 -> convert -> STS, transient registers only
            char* abase = smem + s * STAGE;
            #pragma unroll
            for (int it = 0; it < (MT * CPR) / THREADS; it++) {
                int g = it * THREADS + tid;
                int r = g / CPR, c = g - r * CPR;
                int k0 = kt * BK + c * 8;
                float4 v0 = make_float4(0.f, 0.f, 0.f, 0.f), v1 = v0;
                if ((m0 + r < M_REAL) && (k0 < IN_DIM)) {
                    const float4* p = reinterpret_cast<const float4*>(
                        Xfp + (size_t)(m0 + r) * lda + k0);
                    v0 = p[0];
                    v1 = p[1];
                }
                uint32_t hw[4];
                hw[0] = pack_h2(__float2half(v0.x), __float2half(v0.y));
                hw[1] = pack_h2(__float2half(v0.z), __float2half(v0.w));
                hw[2] = pack_h2(__float2half(v1.x), __float2half(v1.y));
                hw[3] = pack_h2(__float2half(v1.z), __float2half(v1.w));
                *reinterpret_cast<uint4*>(abase + toff(r, c)) =
                    make_uint4(hw[0], hw[1], hw[2], hw[3]);
            }
        } else {
            const uint32_t abase = sbase + s * STAGE;
            #pragma unroll
            for (int it = 0; it < (MT * CPR) / THREADS; it++) {
                int g = it * THREADS + tid;
                int r = g / CPR, c = g - r * CPR;
                const __half* src = A + (size_t)(m0 + r) * lda + kt * BK + c * 8;
                cp16(abase + toff(r, c), src);
            }
        }
        asm volatile("cp.async.commit_group;" ::: "memory");
    };

    // ---------------- prologue: stages 0,1 ----------------
    prefetch(0, 0);
    prefetch(1, 1);

    // ---------------- main loop ----------------
    for (int kt = 0; kt < ktiles; kt++) {
        const int s = kt % NSTAGE;
        asm volatile("cp.async.wait_group 1;" ::: "memory");
        __syncthreads();

        const int nk = kt + 2;
        if (nk < ktiles) {
            prefetch(nk, nk % NSTAGE);
        } else {
            // empty group keeps the wait_group accounting aligned so the
            // stage consumed by the LAST iterations is actually drained
            asm volatile("cp.async.commit_group;" ::: "memory");
        }

        const uint32_t sa = sbase + s * STAGE;
        const uint32_t sb = sa + A_B;

        #pragma unroll
        for (int ks = 0; ks < KS_PER; ks++) {
            const uint32_t aoff = (uint32_t)row_a * ROWB +
                                  (uint32_t)((((ks << 1) + csel_a) ^ swz_a) << 4);
            const uint32_t boff = (uint32_t)row_b * ROWB +
                                  (uint32_t)((((ks << 1) + csel_b) ^ swz_b) << 4);
            uint32_t ah[MF][4], bb[NF][2];
            #pragma unroll
            for (int mf = 0; mf < MF; mf++)
                ldsm4(sa + aoff + mf * 16 * ROWB,
                      ah[mf][0], ah[mf][1], ah[mf][2], ah[mf][3]);
            #pragma unroll
            for (int nf2 = 0; nf2 < NF / 2; nf2++) {
                uint32_t r0, r1, r2, r3;
                ldsm4(sb + boff + nf2 * 16 * ROWB, r0, r1, r2, r3);
                bb[2 * nf2][0] = r0; bb[2 * nf2][1] = r1;
                bb[2 * nf2 + 1][0] = r2; bb[2 * nf2 + 1][1] = r3;
            }
            #pragma unroll
            for (int mf = 0; mf < MF; mf++)
                #pragma unroll
                for (int nf = 0; nf < NF; nf++)
                    mma16816(acc[mf][nf], ah[mf], bb[nf]);
            if constexpr (BSPLIT) {
                #pragma unroll
                for (int nf2 = 0; nf2 < NF / 2; nf2++) {
                    uint32_t r0, r1, r2, r3;
                    ldsm4(sb + B_B + boff + nf2 * 16 * ROWB, r0, r1, r2, r3);
                    bb[2 * nf2][0] = r0; bb[2 * nf2][1] = r1;
                    bb[2 * nf2 + 1][0] = r2; bb[2 * nf2 + 1][1] = r3;
                }
                #pragma unroll
                for (int mf = 0; mf < MF; mf++)
                    #pragma unroll
                    for (int nf = 0; nf < NF; nf++)
                        mma16816(acc[mf][nf], ah[mf], bb[nf]);
            }
        }
    }

    // ---------------- epilogue: bias + ReLU + store ----------------
    const int gid = lane >> 2;
    const int tig = lane & 3;
    #pragma unroll
    for (int mf = 0; mf < MF; mf++) {
        #pragma unroll
        for (int nf = 0; nf < NF; nf++) {
            const int col0 = warp_n * WN + nf * 8 + tig * 2;
            const float bv0 = sbias[col0], bv1 = sbias[col0 + 1];
            #pragma unroll
            for (int half = 0; half < 2; half++) {
                const int m = m0 + warp_m * WM + mf * 16 + gid + half * 8;
                float v0 = fmaxf(acc[mf][nf][2 * half + 0] + bv0, 0.0f);
                float v1 = fmaxf(acc[mf][nf][2 * half + 1] + bv1, 0.0f);
                if (m < M_REAL) {
                    if constexpr (OUT_FP32) {
                        if (col0 < LAT)     Ofp[(size_t)m * ldo + col0]     = v0;
                        if (col0 + 1 < LAT) Ofp[(size_t)m * ldo + col0 + 1] = v1;
                    } else {
                        const size_t idx = (size_t)m * ldo + n0 + col0;
                        *reinterpret_cast<uint32_t*>(Oh + idx) =
                            pack_h2(__float2half(v0), __float2half(v1));
                    }
                }
            }
        }
    }
}

// ---------------------------------------------------------------------------
// Host launch
// ---------------------------------------------------------------------------
extern "C" void kernel_launch(void* const* d_in, const int* in_sizes, int n_in,
                              void* d_out, int out_size) {
    const float* X  = (const float*)d_in[0];
    // d_in[1] = g (dead)
    const float* W0 = (const float*)d_in[2];
    const float* b0 = (const float*)d_in[3];
    const float* W1 = (const float*)d_in[4];
    const float* b1 = (const float*)d_in[5];
    const float* W2 = (const float*)d_in[6];
    const float* b2 = (const float*)d_in[7];
    const float* W3 = (const float*)d_in[8];
    const float* b3 = (const float*)d_in[9];
    float* out = (float*)d_out;

    void *w0h, *w1h, *w2h, *w3h, *w3l, *ha, *hb;
    cudaGetSymbolAddress(&w0h, g_W0h);
    cudaGetSymbolAddress(&w1h, g_W1h);
    cudaGetSymbolAddress(&w2h, g_W2h);
    cudaGetSymbolAddress(&w3h, g_W3h); cudaGetSymbolAddress(&w3l, g_W3l);
    cudaGetSymbolAddress(&ha, g_Ha);   cudaGetSymbolAddress(&hb, g_Hb);

    // single fused weight-prep launch
    constexpr int PREP_BLOCKS =
        HID * IN_PAD / 256 + HID * HID / 256 + HID * HID / 256 + 32 * HID / 256;
    prep_all<<<PREP_BLOCKS, 256>>>(
        W0, W1, W2, W3,
        (__half*)w0h, (__half*)w1h, (__half*)w2h, (__half*)w3h, (__half*)w3l);

    const int mtiles = (M_REAL + MT - 1) / MT;  // 782

    // smem sizes (3 stages + bias)
    constexpr int SM_1P = 3 * (MT * 128 + 128 * 128) + 128 * 4;      // 98816
    constexpr int SM_L3 = 3 * (MT * 128 + 2 * 32 * 128) + 32 * 4;    // 73856

    cudaFuncSetAttribute((const void*)mlp_gemm<128, 64, 2, 4, 2, false, true, false>,
                         cudaFuncAttributeMaxDynamicSharedMemorySize, SM_1P);
    cudaFuncSetAttribute((const void*)mlp_gemm<128, 64, 2, 4, 2, false, false, false>,
                         cudaFuncAttributeMaxDynamicSharedMemorySize, SM_1P);
    cudaFuncSetAttribute((const void*)mlp_gemm<32, 64, 4, 2, 1, true, false, true>,
                         cudaFuncAttributeMaxDynamicSharedMemorySize, SM_L3);

    // layer 0: X fp32 (inline fp16 convert) x W0 fp16, 1-pass, BN=128
    mlp_gemm<128, 64, 2, 4, 2, false, true, false><<<dim3(4, mtiles), 256, SM_1P>>>(
        X, nullptr, IN_DIM,
        (const __half*)w0h, nullptr, IN_PAD,
        b0, HID,
        (__half*)ha, nullptr, HID, IN_PAD / 64);

    // layer 1: Ha x W1, 1-pass
    mlp_gemm<128, 64, 2, 4, 2, false, false, false><<<dim3(4, mtiles), 256, SM_1P>>>(
        nullptr, (const __half*)ha, HID,
        (const __half*)w1h, nullptr, HID,
        b1, HID,
        (__half*)hb, nullptr, HID, HID / 64);

    // layer 2: Hb x W2, 1-pass
    mlp_gemm<128, 64, 2, 4, 2, false, false, false><<<dim3(4, mtiles), 256, SM_1P>>>(
        nullptr, (const __half*)hb, HID,
        (const __half*)w2h, nullptr, HID,
        b2, HID,
        (__half*)ha, nullptr, HID, HID / 64);

    // layer 3: Ha x (W3h + W3l), 2-pass exact-split B, fp32 out [100000, 20]
    mlp_gemm<32, 64, 4, 2, 1, true, false, true><<<dim3(1, mtiles), 256, SM_L3>>>(
        nullptr, (const __half*)ha, HID,
        (const __half*)w3h, (const __half*)w3l, HID,
        b3, LAT,
        nullptr, out, LAT, HID / 64);

    (void)in_sizes; (void)n_in; (void)out_size;
}

// round 17
// speedup vs baseline: 2.2411x; 1.1115x over previous
#include <cuda_runtime.h>
#include <cuda_fp16.h>
#include <cstdint>
#include <cstddef>

// ---------------------------------------------------------------------------
// Problem constants
// ---------------------------------------------------------------------------
static constexpr int IN_DIM  = 3000;
static constexpr int IN_PAD  = 3008;    // K padded to multiple of 64
static constexpr int HID     = 512;
static constexpr int LAT     = 20;
static constexpr int M_REAL  = 100000;
static constexpr int M_PAD   = 100096;  // 782 * 128
static constexpr int MT      = 128;     // CTA M tile

// ---------------------------------------------------------------------------
// Static device scratch (allocation-free rule)
// ---------------------------------------------------------------------------
__device__ __align__(16) __half g_W0h[HID * IN_PAD];
__device__ __align__(16) __half g_W1h[HID * HID];
__device__ __align__(16) __half g_W2h[HID * HID];
__device__ __align__(16) __half g_W3h[32 * HID];
__device__ __align__(16) __half g_W3l[32 * HID];
__device__ __align__(16) __half g_Ha[(size_t)M_PAD * HID];
__device__ __align__(16) __half g_Hb[(size_t)M_PAD * HID];

// ---------------------------------------------------------------------------
// Helpers
// ---------------------------------------------------------------------------
__device__ __forceinline__ uint32_t smem_u32(const void* p) {
    uint32_t a;
    asm("{ .reg .u64 t; cvta.to.shared.u64 t, %1; cvt.u32.u64 %0, t; }"
        : "=r"(a) : "l"(p));
    return a;
}

__device__ __forceinline__ void cp16(uint32_t dst, const void* src) {
    asm volatile("cp.async.cg.shared.global [%0], [%1], 16;"
                 :: "r"(dst), "l"(src) : "memory");
}

__device__ __forceinline__ void ldsm4(uint32_t addr, uint32_t& r0, uint32_t& r1,
                                      uint32_t& r2, uint32_t& r3) {
    asm volatile("ldmatrix.sync.aligned.m8n8.x4.shared.b16 {%0,%1,%2,%3}, [%4];"
                 : "=r"(r0), "=r"(r1), "=r"(r2), "=r"(r3) : "r"(addr));
}

__device__ __forceinline__ void mma16816(float* c, const uint32_t* a, const uint32_t* b) {
    asm volatile(
        "mma.sync.aligned.m16n8k16.row.col.f32.f16.f16.f32 "
        "{%0,%1,%2,%3}, {%4,%5,%6,%7}, {%8,%9}, {%0,%1,%2,%3};"
        : "+f"(c[0]), "+f"(c[1]), "+f"(c[2]), "+f"(c[3])
        : "r"(a[0]), "r"(a[1]), "r"(a[2]), "r"(a[3]), "r"(b[0]), "r"(b[1]));
}

__device__ __forceinline__ void split1(float v, __half& h, __half& l) {
    h = __float2half(v);
    l = __float2half(v - __half2float(h));
}

__device__ __forceinline__ uint32_t pack_h2(__half a, __half b) {
    __half2 t = __halves2half2(a, b);  // .x = a (low half)
    return *reinterpret_cast<uint32_t*>(&t);
}

// ---------------------------------------------------------------------------
// Fused weight prep (one launch)
// ---------------------------------------------------------------------------
__device__ __forceinline__ void prep_h(const float* W, __half* dh,
                                       int K, int N, int K_pad, int idx) {
    int n = idx / K_pad, k = idx - n * K_pad;
    float v = (n < N && k < K) ? W[(size_t)k * N + n] : 0.0f;
    dh[idx] = __float2half(v);
}

__global__ void prep_all(const float* W0, const float* W1, const float* W2,
                         const float* W3,
                         __half* w0h, __half* w1h, __half* w2h,
                         __half* w3h, __half* w3l) {
    constexpr int B0 = HID * IN_PAD / 256;       // 6016
    constexpr int B1 = B0 + HID * HID / 256;     // 7040
    constexpr int B2 = B1 + HID * HID / 256;     // 8064
    int b = blockIdx.x;
    int t = threadIdx.x;
    if (b < B0) {
        prep_h(W0, w0h, IN_DIM, HID, IN_PAD, b * 256 + t);
    } else if (b < B1) {
        prep_h(W1, w1h, HID, HID, HID, (b - B0) * 256 + t);
    } else if (b < B2) {
        prep_h(W2, w2h, HID, HID, HID, (b - B1) * 256 + t);
    } else {
        int idx = (b - B2) * 256 + t;
        int n = idx / HID, k = idx - n * HID;
        float v = (n < LAT) ? W3[(size_t)k * LAT + n] : 0.0f;
        __half h, l;
        split1(v, h, l);
        w3h[idx] = h;
        w3l[idx] = l;
    }
}

// ---------------------------------------------------------------------------
// fp16 GEMM + bias + ReLU via mma.sync m16n8k16
//   BSPLIT=false: D = A*B            (1 pass)
//   BSPLIT=true : D = A*Bh + A*Bl    (2 passes, exact-split B)
// Grid = (ntiles, mtiles). 3-stage cp.async pipeline. Main layers: 128-thread
// CTAs with 64x64 warp tiles (R = 1/WM + 1/WN minimized -> smem crossbar
// relief) and 2 CTAs/SM (RF: 65536/(2*128) = 256 regs/thread available).
// PIPELINE INVARIANT: exactly one commit_group per loop iteration (empty when
// not prefetching) so wait_group 1 always drains the stage consumed next.
// ---------------------------------------------------------------------------
template <int BN, int BK, int WARPS_M, int WARPS_N, int MIN_CTAS, bool BSPLIT,
          bool A_FP32, bool OUT_FP32>
__global__ void __launch_bounds__(WARPS_M * WARPS_N * 32, MIN_CTAS)
mlp_gemm(const float* __restrict__ Xfp,
         const __half* __restrict__ A, int lda,
         const __half* __restrict__ Bh,
         const __half* __restrict__ Bl, int ldb,
         const float* __restrict__ bias, int n_bias,
         __half* __restrict__ Oh,
         float* __restrict__ Ofp, int ldo,
         int ktiles) {
    constexpr int THREADS = WARPS_M * WARPS_N * 32;
    constexpr int WM = MT / WARPS_M;
    constexpr int WN = BN / WARPS_N;
    constexpr int MF = WM / 16;
    constexpr int NF = WN / 8;
    constexpr int CPR = BK / 8;            // 16B chunks per row
    constexpr int ROWB = 2 * BK;           // row bytes
    constexpr int SWS = (BK == 64) ? 0 : 1;
    constexpr int NBBUF = BSPLIT ? 2 : 1;
    constexpr int A_B = MT * ROWB;
    constexpr int B_B = BN * ROWB;
    constexpr int STAGE = A_B + NBBUF * B_B;
    constexpr int NSTAGE = 3;
    constexpr int KS_PER = BK / 16;

    extern __shared__ __align__(128) char smem[];
    float* sbias = reinterpret_cast<float*>(smem + NSTAGE * STAGE);
    const uint32_t sbase = smem_u32(smem);

    const int tid = threadIdx.x;
    const int wid = tid >> 5;
    const int lane = tid & 31;
    const int warp_m = wid % WARPS_M;
    const int warp_n = wid / WARPS_M;
    const int n0 = blockIdx.x * BN;    // N-tile fast -> group shares A via L2
    const int m0 = blockIdx.y * MT;

    for (int i = tid; i < BN; i += THREADS)
        sbias[i] = (n0 + i < n_bias) ? bias[n0 + i] : 0.0f;

    auto toff = [](int r, int c) -> uint32_t {
        return (uint32_t)(r * ROWB + (((c ^ ((r >> SWS) & (CPR - 1)))) << 4));
    };

    // ldmatrix lane geometry (validated rounds 3-15)
    const int row_a = warp_m * WM + ((lane & 7) | (((lane >> 3) & 1) << 3));
    const int csel_a = lane >> 4;
    const int swz_a = (row_a >> SWS) & (CPR - 1);
    const int row_b = warp_n * WN + ((lane & 7) | (((lane >> 4) & 1) << 3));
    const int csel_b = (lane >> 3) & 1;
    const int swz_b = (row_b >> SWS) & (CPR - 1);

    float acc[MF][NF][4] = {};

    // ---------------- tile prefetch (one stage, one commit) ----------------
    auto prefetch = [&](int kt, int s) {
        const uint32_t bbase = sbase + s * STAGE + A_B;
        #pragma unroll
        for (int it = 0; it < (NBBUF * BN * CPR) / THREADS; it++) {
            int g = it * THREADS + tid;
            int buf = g / (BN * CPR);
            int w = g - buf * (BN * CPR);
            int r = w / CPR, c = w - r * CPR;
            const __half* src =
                (buf ? Bl : Bh) + (size_t)(n0 + r) * ldb + kt * BK + c * 8;
            cp16(bbase + buf * B_B + toff(r, c), src);
        }
        if constexpr (A_FP32) {
            // LDG fp32 -> convert -> STS, transient registers only
            char* abase = smem + s * STAGE;
            #pragma unroll
            for (int it = 0; it < (MT * CPR) / THREADS; it++) {
                int g = it * THREADS + tid;
                int r = g / CPR, c = g - r * CPR;
                int k0 = kt * BK + c * 8;
                float4 v0 = make_float4(0.f, 0.f, 0.f, 0.f), v1 = v0;
                if ((m0 + r < M_REAL) && (k0 < IN_DIM)) {
                    const float4* p = reinterpret_cast<const float4*>(
                        Xfp + (size_t)(m0 + r) * lda + k0);
                    v0 = p[0];
                    v1 = p[1];
                }
                uint32_t hw[4];
                hw[0] = pack_h2(__float2half(v0.x), __float2half(v0.y));
                hw[1] = pack_h2(__float2half(v0.z), __float2half(v0.w));
                hw[2] = pack_h2(__float2half(v1.x), __float2half(v1.y));
                hw[3] = pack_h2(__float2half(v1.z), __float2half(v1.w));
                *reinterpret_cast<uint4*>(abase + toff(r, c)) =
                    make_uint4(hw[0], hw[1], hw[2], hw[3]);
            }
        } else {
            const uint32_t abase = sbase + s * STAGE;
            #pragma unroll
            for (int it = 0; it < (MT * CPR) / THREADS; it++) {
                int g = it * THREADS + tid;
                int r = g / CPR, c = g - r * CPR;
                const __half* src = A + (size_t)(m0 + r) * lda + kt * BK + c * 8;
                cp16(abase + toff(r, c), src);
            }
        }
        asm volatile("cp.async.commit_group;" ::: "memory");
    };

    // ---------------- prologue: stages 0,1 ----------------
    prefetch(0, 0);
    prefetch(1, 1);

    // ---------------- main loop ----------------
    for (int kt = 0; kt < ktiles; kt++) {
        const int s = kt % NSTAGE;
        asm volatile("cp.async.wait_group 1;" ::: "memory");
        __syncthreads();

        const int nk = kt + 2;
        if (nk < ktiles) {
            prefetch(nk, nk % NSTAGE);
        } else {
            // empty group keeps the wait_group accounting aligned so the
            // stage consumed by the LAST iterations is actually drained
            asm volatile("cp.async.commit_group;" ::: "memory");
        }

        const uint32_t sa = sbase + s * STAGE;
        const uint32_t sb = sa + A_B;

        #pragma unroll
        for (int ks = 0; ks < KS_PER; ks++) {
            const uint32_t aoff = (uint32_t)row_a * ROWB +
                                  (uint32_t)((((ks << 1) + csel_a) ^ swz_a) << 4);
            const uint32_t boff = (uint32_t)row_b * ROWB +
                                  (uint32_t)((((ks << 1) + csel_b) ^ swz_b) << 4);
            uint32_t ah[MF][4], bb[NF][2];
            #pragma unroll
            for (int mf = 0; mf < MF; mf++)
                ldsm4(sa + aoff + mf * 16 * ROWB,
                      ah[mf][0], ah[mf][1], ah[mf][2], ah[mf][3]);
            #pragma unroll
            for (int nf2 = 0; nf2 < NF / 2; nf2++) {
                uint32_t r0, r1, r2, r3;
                ldsm4(sb + boff + nf2 * 16 * ROWB, r0, r1, r2, r3);
                bb[2 * nf2][0] = r0; bb[2 * nf2][1] = r1;
                bb[2 * nf2 + 1][0] = r2; bb[2 * nf2 + 1][1] = r3;
            }
            #pragma unroll
            for (int mf = 0; mf < MF; mf++)
                #pragma unroll
                for (int nf = 0; nf < NF; nf++)
                    mma16816(acc[mf][nf], ah[mf], bb[nf]);
            if constexpr (BSPLIT) {
                #pragma unroll
                for (int nf2 = 0; nf2 < NF / 2; nf2++) {
                    uint32_t r0, r1, r2, r3;
                    ldsm4(sb + B_B + boff + nf2 * 16 * ROWB, r0, r1, r2, r3);
                    bb[2 * nf2][0] = r0; bb[2 * nf2][1] = r1;
                    bb[2 * nf2 + 1][0] = r2; bb[2 * nf2 + 1][1] = r3;
                }
                #pragma unroll
                for (int mf = 0; mf < MF; mf++)
                    #pragma unroll
                    for (int nf = 0; nf < NF; nf++)
                        mma16816(acc[mf][nf], ah[mf], bb[nf]);
            }
        }
    }

    // ---------------- epilogue: bias + ReLU + store ----------------
    const int gid = lane >> 2;
    const int tig = lane & 3;
    #pragma unroll
    for (int mf = 0; mf < MF; mf++) {
        #pragma unroll
        for (int nf = 0; nf < NF; nf++) {
            const int col0 = warp_n * WN + nf * 8 + tig * 2;
            const float bv0 = sbias[col0], bv1 = sbias[col0 + 1];
            #pragma unroll
            for (int half = 0; half < 2; half++) {
                const int m = m0 + warp_m * WM + mf * 16 + gid + half * 8;
                float v0 = fmaxf(acc[mf][nf][2 * half + 0] + bv0, 0.0f);
                float v1 = fmaxf(acc[mf][nf][2 * half + 1] + bv1, 0.0f);
                if (m < M_REAL) {
                    if constexpr (OUT_FP32) {
                        if (col0 < LAT)     Ofp[(size_t)m * ldo + col0]     = v0;
                        if (col0 + 1 < LAT) Ofp[(size_t)m * ldo + col0 + 1] = v1;
                    } else {
                        const size_t idx = (size_t)m * ldo + n0 + col0;
                        *reinterpret_cast<uint32_t*>(Oh + idx) =
                            pack_h2(__float2half(v0), __float2half(v1));
                    }
                }
            }
        }
    }
}

// ---------------------------------------------------------------------------
// Host launch
// ---------------------------------------------------------------------------
extern "C" void kernel_launch(void* const* d_in, const int* in_sizes, int n_in,
                              void* d_out, int out_size) {
    const float* X  = (const float*)d_in[0];
    // d_in[1] = g (dead)
    const float* W0 = (const float*)d_in[2];
    const float* b0 = (const float*)d_in[3];
    const float* W1 = (const float*)d_in[4];
    const float* b1 = (const float*)d_in[5];
    const float* W2 = (const float*)d_in[6];
    const float* b2 = (const float*)d_in[7];
    const float* W3 = (const float*)d_in[8];
    const float* b3 = (const float*)d_in[9];
    float* out = (float*)d_out;

    void *w0h, *w1h, *w2h, *w3h, *w3l, *ha, *hb;
    cudaGetSymbolAddress(&w0h, g_W0h);
    cudaGetSymbolAddress(&w1h, g_W1h);
    cudaGetSymbolAddress(&w2h, g_W2h);
    cudaGetSymbolAddress(&w3h, g_W3h); cudaGetSymbolAddress(&w3l, g_W3l);
    cudaGetSymbolAddress(&ha, g_Ha);   cudaGetSymbolAddress(&hb, g_Hb);

    // single fused weight-prep launch
    constexpr int PREP_BLOCKS =
        HID * IN_PAD / 256 + HID * HID / 256 + HID * HID / 256 + 32 * HID / 256;
    prep_all<<<PREP_BLOCKS, 256>>>(
        W0, W1, W2, W3,
        (__half*)w0h, (__half*)w1h, (__half*)w2h, (__half*)w3h, (__half*)w3l);

    const int mtiles = (M_REAL + MT - 1) / MT;  // 782

    // smem sizes (3 stages + bias)
    constexpr int SM_1P = 3 * (MT * 128 + 128 * 128) + 128 * 4;      // 98816
    constexpr int SM_L3 = 3 * (MT * 128 + 2 * 32 * 128) + 32 * 4;    // 73856

    cudaFuncSetAttribute((const void*)mlp_gemm<128, 64, 2, 2, 2, false, true, false>,
                         cudaFuncAttributeMaxDynamicSharedMemorySize, SM_1P);
    cudaFuncSetAttribute((const void*)mlp_gemm<128, 64, 2, 2, 2, false, false, false>,
                         cudaFuncAttributeMaxDynamicSharedMemorySize, SM_1P);
    cudaFuncSetAttribute((const void*)mlp_gemm<32, 64, 4, 2, 1, true, false, true>,
                         cudaFuncAttributeMaxDynamicSharedMemorySize, SM_L3);

    // layer 0: X fp32 (inline fp16 convert) x W0 fp16, 1-pass,
    // 128 threads, warp tile 64x64, 2 CTAs/SM
    mlp_gemm<128, 64, 2, 2, 2, false, true, false><<<dim3(4, mtiles), 128, SM_1P>>>(
        X, nullptr, IN_DIM,
        (const __half*)w0h, nullptr, IN_PAD,
        b0, HID,
        (__half*)ha, nullptr, HID, IN_PAD / 64);

    // layer 1: Ha x W1, 1-pass
    mlp_gemm<128, 64, 2, 2, 2, false, false, false><<<dim3(4, mtiles), 128, SM_1P>>>(
        nullptr, (const __half*)ha, HID,
        (const __half*)w1h, nullptr, HID,
        b1, HID,
        (__half*)hb, nullptr, HID, HID / 64);

    // layer 2: Hb x W2, 1-pass
    mlp_gemm<128, 64, 2, 2, 2, false, false, false><<<dim3(4, mtiles), 128, SM_1P>>>(
        nullptr, (const __half*)hb, HID,
        (const __half*)w2h, nullptr, HID,
        b2, HID,
        (__half*)ha, nullptr, HID, HID / 64);

    // layer 3: Ha x (W3h + W3l), 2-pass exact-split B, fp32 out [100000, 20]
    mlp_gemm<32, 64, 4, 2, 1, true, false, true><<<dim3(1, mtiles), 256, SM_L3>>>(
        nullptr, (const __half*)ha, HID,
        (const __half*)w3h, (const __half*)w3l, HID,
        b3, LAT,
        nullptr, out, LAT, HID / 64);

    (void)in_sizes; (void)n_in; (void)out_size;
}